// round 2
// baseline (speedup 1.0000x reference)
#include <cuda_runtime.h>
#include <cuda_bf16.h>

#define NN 50000
#define NE 600000
#define HD 128

#define EDGE_SMEM 133632   // (64*260 + 64*132 + 32*260)*4
#define NODE_SMEM 99840    // (64*260 + 32*260)*4
#define P_SMEM    67072    // (64*132 + 32*260)*4

// ---------------- device scratch (no allocations allowed) ----------------
__device__ float g_h[NN * HD];
__device__ float g_ea[(size_t)NE * HD];
__device__ float g_P1[(size_t)NN * 256];
__device__ float g_P2[(size_t)NN * 256];
__device__ float g_agg[NN * HD];
__device__ float g_inv[NN];
__device__ int   g_cnt[NN];
__device__ int   g_row[NE];
__device__ int   g_col[NE];
__device__ int   g_is64;

// ---------------- helpers ----------------
__device__ __forceinline__ float gelu(float x) { return x * normcdff(x); }

__device__ __forceinline__ float warpsum(float s) {
#pragma unroll
    for (int o = 16; o; o >>= 1) s += __shfl_xor_sync(0xffffffffu, s, o);
    return s;
}

// Load a 32 x 256 weight chunk (ld 256) into sW (ld 260)
__device__ __forceinline__ void loadW256(float* sW, const float* __restrict__ W,
                                         int kBase, int tid) {
    for (int t = tid; t < 32 * 64; t += 256) {
        int kk = t >> 6, q = t & 63;
        *(float4*)&sW[kk * 260 + q * 4] =
            *(const float4*)&W[(size_t)(kBase + kk) * 256 + q * 4];
    }
}

// Load a 32 x 128 weight chunk (ld 128) into sW (ld 132)
__device__ __forceinline__ void loadW128(float* sW, const float* __restrict__ W,
                                         int kBase, int tid) {
    for (int t = tid; t < 32 * 32; t += 256) {
        int kk = t >> 5, q = t & 31;
        *(float4*)&sW[kk * 132 + q * 4] =
            *(const float4*)&W[(size_t)(kBase + kk) * 128 + q * 4];
    }
}

// Register-blocked 32-k microkernel. Thread (tr,tc): rows tr*8..+7, cols tc*NC..+NC-1.
template <int NC>
__device__ __forceinline__ void mm32(const float* __restrict__ sA, int ldA, int kOff,
                                     const float* __restrict__ sW, int ldW,
                                     int tr, int tc, float (&acc)[8][NC]) {
#pragma unroll
    for (int kk = 0; kk < 32; kk += 4) {
        float4 a4[8];
#pragma unroll
        for (int u = 0; u < 8; u++)
            a4[u] = *(const float4*)&sA[(tr * 8 + u) * ldA + kOff + kk];
#pragma unroll
        for (int d = 0; d < 4; d++) {
            float w[NC];
#pragma unroll
            for (int v = 0; v < NC; v += 4)
                *(float4*)&w[v] = *(const float4*)&sW[(kk + d) * ldW + tc * NC + v];
#pragma unroll
            for (int u = 0; u < 8; u++) {
                float av = (d == 0) ? a4[u].x : (d == 1) ? a4[u].y
                         : (d == 2) ? a4[u].z : a4[u].w;
#pragma unroll
                for (int v = 0; v < NC; v++) acc[u][v] = fmaf(av, w[v], acc[u][v]);
            }
        }
    }
}

// ---------------- index canonicalization ----------------
__global__ void k_detect(const void* __restrict__ ei) {
    if (threadIdx.x == 0) {
        const long long* p = (const long long*)ei;
        int ok = 1;
        for (int i = 0; i < 64; i++) {
            long long v = p[i];
            if (v < 0 || v >= NN) { ok = 0; break; }
        }
        g_is64 = ok;
    }
}

__global__ void k_convert(const void* __restrict__ ei) {
    int e = blockIdx.x * blockDim.x + threadIdx.x;
    if (e >= NE) return;
    if (g_is64) {
        const long long* p = (const long long*)ei;
        g_row[e] = (int)p[e];
        g_col[e] = (int)p[NE + e];
    } else {
        const int* p = (const int*)ei;
        g_row[e] = p[e];
        g_col[e] = p[NE + e];
    }
}

__global__ void k_deg() {
    int e = blockIdx.x * blockDim.x + threadIdx.x;
    if (e < NE) atomicAdd(&g_cnt[g_col[e]], 1);
}

__global__ void k_inv() {
    int n = blockIdx.x * blockDim.x + threadIdx.x;
    if (n < NN) {
        g_inv[n] = 1.0f / fmaxf((float)g_cnt[n], 1.0f);
        g_cnt[n] = 0;  // restore invariant for next launch
    }
}

// ---------------- encoders ----------------
__global__ void k_enc(const float* __restrict__ x, const float* __restrict__ W,
                      const float* __restrict__ b, const float* __restrict__ g,
                      const float* __restrict__ be) {
    int n = blockIdx.x, j = threadIdx.x;
    __shared__ float sx[8];
    __shared__ float red[8];
    if (j < 7) sx[j] = x[n * 7 + j];
    __syncthreads();
    float a = b[j];
#pragma unroll
    for (int k = 0; k < 7; k++) a = fmaf(sx[k], W[k * HD + j], a);
    int w = j >> 5, lane = j & 31;
    float s = warpsum(a);
    if (lane == 0) red[w] = s;
    __syncthreads();
    float m = (red[0] + red[1] + red[2] + red[3]) * (1.0f / HD);
    float d = a - m;
    float q = warpsum(d * d);
    if (lane == 0) red[4 + w] = q;
    __syncthreads();
    float var = (red[4] + red[5] + red[6] + red[7]) * (1.0f / HD);
    float t = d * rsqrtf(var + 1e-5f) * g[j] + be[j];
    g_h[(size_t)n * HD + j] = gelu(t);
}

__global__ void k_ee(const float* __restrict__ ea, const float* __restrict__ W,
                     const float* __restrict__ b) {
    int e = blockIdx.x, j = threadIdx.x;
    __shared__ float sa[8];
    if (j < 8) sa[j] = ea[e * 8 + j];
    __syncthreads();
    float a = b[j];
#pragma unroll
    for (int k = 0; k < 8; k++) a = fmaf(sa[k], W[k * HD + j], a);
    g_ea[(size_t)e * HD + j] = a;
}

// ---------------- node projections P1 = h@W1a + b1, P2 = h@W1b ----------------
__global__ void __launch_bounds__(256, 1) k_P(const float* __restrict__ W,
                                              const float* __restrict__ b1) {
    extern __shared__ float sm[];
    float* sA = sm;             // 64 x 132
    float* sW = sm + 64 * 132;  // 32 x 260
    int tid = threadIdx.x, tc = tid & 31, tr = tid >> 5;
    int base = blockIdx.x * 64;
    int part = blockIdx.y;
    const float* Wp = W + (size_t)part * 128 * 256;
    float* out = part ? g_P2 : g_P1;

    for (int t = tid; t < 64 * 32; t += 256) {
        int i = t >> 5, q = t & 31;
        int n = base + i;
        float4 v = (n < NN) ? ((const float4*)g_h)[(size_t)n * 32 + q]
                            : make_float4(0, 0, 0, 0);
        *(float4*)&sA[i * 132 + q * 4] = v;
    }
    float acc[8][8];
#pragma unroll
    for (int u = 0; u < 8; u++)
#pragma unroll
        for (int v = 0; v < 8; v++) acc[u][v] = 0.f;
    for (int kc = 0; kc < 4; kc++) {
        __syncthreads();
        loadW256(sW, Wp, kc * 32, tid);
        __syncthreads();
        mm32<8>(sA, 132, kc * 32, sW, 260, tr, tc, acc);
    }
#pragma unroll
    for (int u = 0; u < 8; u++) {
        int n = base + tr * 8 + u;
        if (n < NN) {
            float o[8];
#pragma unroll
            for (int v = 0; v < 8; v++)
                o[v] = acc[u][v] + (part ? 0.f : b1[tc * 8 + v]);
            float4* dst = (float4*)&out[(size_t)n * 256 + tc * 8];
            dst[0] = make_float4(o[0], o[1], o[2], o[3]);
            dst[1] = make_float4(o[4], o[5], o[6], o[7]);
        }
    }
}

// ---------------- fused edge update ----------------
__global__ void __launch_bounds__(256, 1) k_edge(
    const float* __restrict__ W1c, const float* __restrict__ g1,
    const float* __restrict__ bt1, const float* __restrict__ W2,
    const float* __restrict__ b2, const float* __restrict__ g2,
    const float* __restrict__ bt2) {
    extern __shared__ float sm[];
    float* sPre = sm;                // 64 x 260
    float* sEa  = sm + 64 * 260;     // 64 x 132
    float* sW   = sEa + 64 * 132;    // 32 x 260
    __shared__ int sRow[64];
    __shared__ int sCol[64];
    int tid = threadIdx.x, tc = tid & 31, tr = tid >> 5;
    int base = blockIdx.x * 64;  // NE = 9375 * 64 exactly

    if (tid < 64) { sRow[tid] = g_row[base + tid]; sCol[tid] = g_col[base + tid]; }
    __syncthreads();

    for (int t = tid; t < 64 * 64; t += 256) {  // pre = P1[row] + P2[col]
        int e = t >> 6, q = t & 63;
        float4 v1 = ((const float4*)g_P1)[(size_t)sRow[e] * 64 + q];
        float4 v2 = ((const float4*)g_P2)[(size_t)sCol[e] * 64 + q];
        v1.x += v2.x; v1.y += v2.y; v1.z += v2.z; v1.w += v2.w;
        *(float4*)&sPre[e * 260 + q * 4] = v1;
    }
    for (int t = tid; t < 64 * 32; t += 256) {  // ea tile
        int e = t >> 5, q = t & 31;
        *(float4*)&sEa[e * 132 + q * 4] = ((const float4*)g_ea)[(size_t)(base + e) * 32 + q];
    }
    __syncthreads();

    // GEMM1: acc = pre + ea @ W1c  (K=128)
    float acc[8][8];
#pragma unroll
    for (int u = 0; u < 8; u++)
#pragma unroll
        for (int v = 0; v < 8; v++) acc[u][v] = sPre[(tr * 8 + u) * 260 + tc * 8 + v];
    for (int kc = 0; kc < 4; kc++) {
        __syncthreads();
        loadW256(sW, W1c, kc * 32, tid);
        __syncthreads();
        mm32<8>(sEa, 132, kc * 32, sW, 260, tr, tc, acc);
    }

    // LN(256) + GELU, write t into sPre
    float g1v[8], b1v[8];
#pragma unroll
    for (int v = 0; v < 8; v++) { g1v[v] = g1[tc * 8 + v]; b1v[v] = bt1[tc * 8 + v]; }
#pragma unroll
    for (int u = 0; u < 8; u++) {
        float s = 0;
#pragma unroll
        for (int v = 0; v < 8; v++) s += acc[u][v];
        float m = warpsum(s) * (1.0f / 256);
        float q = 0;
#pragma unroll
        for (int v = 0; v < 8; v++) { float d = acc[u][v] - m; q += d * d; }
        float rn = rsqrtf(warpsum(q) * (1.0f / 256) + 1e-5f);
#pragma unroll
        for (int v = 0; v < 8; v++) {
            float t = (acc[u][v] - m) * rn * g1v[v] + b1v[v];
            sPre[(tr * 8 + u) * 260 + tc * 8 + v] = gelu(t);
        }
    }

    // GEMM2: t @ W2 (K=256, out 128)
    float acc2[8][4];
#pragma unroll
    for (int u = 0; u < 8; u++)
#pragma unroll
        for (int v = 0; v < 4; v++) acc2[u][v] = 0.f;
    for (int kc = 0; kc < 8; kc++) {
        __syncthreads();
        loadW128(sW, W2, kc * 32, tid);
        __syncthreads();
        mm32<4>(sPre, 260, kc * 32, sW, 132, tr, tc, acc2);
    }

    float b2v[4], g2v[4], bt2v[4];
#pragma unroll
    for (int v = 0; v < 4; v++) {
        b2v[v] = b2[tc * 4 + v]; g2v[v] = g2[tc * 4 + v]; bt2v[v] = bt2[tc * 4 + v];
    }
#pragma unroll
    for (int u = 0; u < 8; u++) {
        int row = tr * 8 + u;
#pragma unroll
        for (int v = 0; v < 4; v++) acc2[u][v] += b2v[v];
        float s = acc2[u][0] + acc2[u][1] + acc2[u][2] + acc2[u][3];
        float m = warpsum(s) * (1.0f / 128);
        float q = 0;
#pragma unroll
        for (int v = 0; v < 4; v++) { float d = acc2[u][v] - m; q += d * d; }
        float rn = rsqrtf(warpsum(q) * (1.0f / 128) + 1e-5f);
        float4 o;
        o.x = sEa[row * 132 + tc * 4 + 0] + (acc2[u][0] - m) * rn * g2v[0] + bt2v[0];
        o.y = sEa[row * 132 + tc * 4 + 1] + (acc2[u][1] - m) * rn * g2v[1] + bt2v[1];
        o.z = sEa[row * 132 + tc * 4 + 2] + (acc2[u][2] - m) * rn * g2v[2] + bt2v[2];
        o.w = sEa[row * 132 + tc * 4 + 3] + (acc2[u][3] - m) * rn * g2v[3] + bt2v[3];
        ((float4*)g_ea)[(size_t)(base + row) * 32 + tc] = o;
        float* ag = &g_agg[(size_t)sCol[row] * HD + tc * 4];
        atomicAdd(ag + 0, o.x);
        atomicAdd(ag + 1, o.y);
        atomicAdd(ag + 2, o.z);
        atomicAdd(ag + 3, o.w);
    }
}

// ---------------- fused node update ----------------
__global__ void __launch_bounds__(256, 1) k_node(
    const float* __restrict__ W1, const float* __restrict__ b1,
    const float* __restrict__ g1, const float* __restrict__ bt1,
    const float* __restrict__ W2, const float* __restrict__ b2,
    const float* __restrict__ g2, const float* __restrict__ bt2) {
    extern __shared__ float sm[];
    float* sA = sm;             // 64 x 260
    float* sW = sm + 64 * 260;  // 32 x 260
    int tid = threadIdx.x, tc = tid & 31, tr = tid >> 5;
    int base = blockIdx.x * 64;

    for (int t = tid; t < 64 * 32; t += 256) {  // h
        int i = t >> 5, q = t & 31;
        int n = base + i;
        float4 v = (n < NN) ? ((const float4*)g_h)[(size_t)n * 32 + q]
                            : make_float4(0, 0, 0, 0);
        *(float4*)&sA[i * 260 + q * 4] = v;
    }
    for (int t = tid; t < 64 * 32; t += 256) {  // agg * inv  (and zero agg)
        int i = t >> 5, q = t & 31;
        int n = base + i;
        float4 v = make_float4(0, 0, 0, 0);
        if (n < NN) {
            float4* ap = (float4*)&g_agg[(size_t)n * HD + q * 4];
            v = *ap;
            float iv = g_inv[n];
            v.x *= iv; v.y *= iv; v.z *= iv; v.w *= iv;
            *ap = make_float4(0, 0, 0, 0);
        }
        *(float4*)&sA[i * 260 + 128 + q * 4] = v;
    }
    __syncthreads();

    float acc[8][8];
#pragma unroll
    for (int u = 0; u < 8; u++)
#pragma unroll
        for (int v = 0; v < 8; v++) acc[u][v] = 0.f;
    for (int kc = 0; kc < 8; kc++) {
        __syncthreads();
        loadW256(sW, W1, kc * 32, tid);
        __syncthreads();
        mm32<8>(sA, 260, kc * 32, sW, 260, tr, tc, acc);
    }

    float g1v[8], b1v[8], bb[8];
#pragma unroll
    for (int v = 0; v < 8; v++) {
        bb[v] = b1[tc * 8 + v]; g1v[v] = g1[tc * 8 + v]; b1v[v] = bt1[tc * 8 + v];
    }
#pragma unroll
    for (int u = 0; u < 8; u++) {
#pragma unroll
        for (int v = 0; v < 8; v++) acc[u][v] += bb[v];
        float s = 0;
#pragma unroll
        for (int v = 0; v < 8; v++) s += acc[u][v];
        float m = warpsum(s) * (1.0f / 256);
        float q = 0;
#pragma unroll
        for (int v = 0; v < 8; v++) { float d = acc[u][v] - m; q += d * d; }
        float rn = rsqrtf(warpsum(q) * (1.0f / 256) + 1e-5f);
#pragma unroll
        for (int v = 0; v < 8; v++) {
            float t = (acc[u][v] - m) * rn * g1v[v] + b1v[v];
            acc[u][v] = gelu(t);
        }
    }

    // grab residual (h cols tc*4..+3) before overwriting sA with t
    float4 hres[8];
#pragma unroll
    for (int u = 0; u < 8; u++)
        hres[u] = *(float4*)&sA[(tr * 8 + u) * 260 + tc * 4];
    __syncwarp();
#pragma unroll
    for (int u = 0; u < 8; u++)
#pragma unroll
        for (int v = 0; v < 8; v++)
            sA[(tr * 8 + u) * 260 + tc * 8 + v] = acc[u][v];

    float acc2[8][4];
#pragma unroll
    for (int u = 0; u < 8; u++)
#pragma unroll
        for (int v = 0; v < 4; v++) acc2[u][v] = 0.f;
    for (int kc = 0; kc < 8; kc++) {
        __syncthreads();
        loadW128(sW, W2, kc * 32, tid);
        __syncthreads();
        mm32<4>(sA, 260, kc * 32, sW, 132, tr, tc, acc2);
    }

    float b2v[4], g2v[4], bt2v[4];
#pragma unroll
    for (int v = 0; v < 4; v++) {
        b2v[v] = b2[tc * 4 + v]; g2v[v] = g2[tc * 4 + v]; bt2v[v] = bt2[tc * 4 + v];
    }
#pragma unroll
    for (int u = 0; u < 8; u++) {
        int n = base + tr * 8 + u;
#pragma unroll
        for (int v = 0; v < 4; v++) acc2[u][v] += b2v[v];
        float s = acc2[u][0] + acc2[u][1] + acc2[u][2] + acc2[u][3];
        float m = warpsum(s) * (1.0f / 128);
        float q = 0;
#pragma unroll
        for (int v = 0; v < 4; v++) { float d = acc2[u][v] - m; q += d * d; }
        float rn = rsqrtf(warpsum(q) * (1.0f / 128) + 1e-5f);
        float4 o;
        o.x = hres[u].x + (acc2[u][0] - m) * rn * g2v[0] + bt2v[0];
        o.y = hres[u].y + (acc2[u][1] - m) * rn * g2v[1] + bt2v[1];
        o.z = hres[u].z + (acc2[u][2] - m) * rn * g2v[2] + bt2v[2];
        o.w = hres[u].w + (acc2[u][3] - m) * rn * g2v[3] + bt2v[3];
        if (n < NN) ((float4*)g_h)[(size_t)n * 32 + tc] = o;
    }
}

// ---------------- decoder ----------------
__global__ void k_dec(const float* __restrict__ W1, const float* __restrict__ b1,
                      const float* __restrict__ W2, const float* __restrict__ b2,
                      float* __restrict__ out) {
    int n = blockIdx.x, j = threadIdx.x;
    __shared__ float sh[128];
    __shared__ float st[128];
    sh[j] = g_h[(size_t)n * HD + j];
    __syncthreads();
    float a = b1[j];
#pragma unroll 8
    for (int k = 0; k < 128; k++) a = fmaf(sh[k], W1[k * HD + j], a);
    st[j] = gelu(a);
    __syncthreads();
    int w = j >> 5, lane = j & 31;
    float s = 0;
#pragma unroll
    for (int k = lane; k < 128; k += 32) s = fmaf(st[k], W2[k * 4 + w], s);
    s = warpsum(s);
    if (lane == 0) out[(size_t)n * 4 + w] = s + b2[w];
}

// ---------------- launch ----------------
extern "C" void kernel_launch(void* const* d_in, const int* in_sizes, int n_in,
                              void* d_out, int out_size) {
    (void)in_sizes; (void)n_in; (void)out_size;
    const void*  ei      = d_in[1];
    const float* x       = (const float*)d_in[0];
    const float* eattr   = (const float*)d_in[2];
    const float* enc_W   = (const float*)d_in[3];
    const float* enc_b   = (const float*)d_in[4];
    const float* enc_g   = (const float*)d_in[5];
    const float* enc_bt  = (const float*)d_in[6];
    const float* ee_W    = (const float*)d_in[7];
    const float* ee_b    = (const float*)d_in[8];
    const float* eW1     = (const float*)d_in[9];
    const float* eb1     = (const float*)d_in[10];
    const float* eg1     = (const float*)d_in[11];
    const float* ebt1    = (const float*)d_in[12];
    const float* eW2     = (const float*)d_in[13];
    const float* eb2     = (const float*)d_in[14];
    const float* eg2     = (const float*)d_in[15];
    const float* ebt2    = (const float*)d_in[16];
    const float* nW1     = (const float*)d_in[17];
    const float* nb1     = (const float*)d_in[18];
    const float* ng1     = (const float*)d_in[19];
    const float* nbt1    = (const float*)d_in[20];
    const float* nW2     = (const float*)d_in[21];
    const float* nb2     = (const float*)d_in[22];
    const float* ng2     = (const float*)d_in[23];
    const float* nbt2    = (const float*)d_in[24];
    const float* dec_W1  = (const float*)d_in[25];
    const float* dec_b1  = (const float*)d_in[26];
    const float* dec_W2  = (const float*)d_in[27];
    const float* dec_b2  = (const float*)d_in[28];

    cudaFuncSetAttribute(k_edge, cudaFuncAttributeMaxDynamicSharedMemorySize, EDGE_SMEM);
    cudaFuncSetAttribute(k_node, cudaFuncAttributeMaxDynamicSharedMemorySize, NODE_SMEM);
    cudaFuncSetAttribute(k_P,    cudaFuncAttributeMaxDynamicSharedMemorySize, P_SMEM);

    k_detect<<<1, 32>>>(ei);
    k_convert<<<(NE + 255) / 256, 256>>>(ei);
    k_deg<<<(NE + 255) / 256, 256>>>();
    k_inv<<<(NN + 255) / 256, 256>>>();
    k_enc<<<NN, 128>>>(x, enc_W, enc_b, enc_g, enc_bt);
    k_ee<<<NE, 128>>>(eattr, ee_W, ee_b);

    const int nodeBlocks = (NN + 63) / 64;  // 782
    for (int l = 0; l < 10; l++) {
        const float* W1l = eW1 + (size_t)l * 384 * 256;
        k_P<<<dim3(nodeBlocks, 2), 256, P_SMEM>>>(W1l, eb1 + l * 256);
        k_edge<<<NE / 64, 256, EDGE_SMEM>>>(
            W1l + 256 * 256, eg1 + l * 256, ebt1 + l * 256,
            eW2 + (size_t)l * 256 * 128, eb2 + l * 128,
            eg2 + l * 128, ebt2 + l * 128);
        k_node<<<nodeBlocks, 256, NODE_SMEM>>>(
            nW1 + (size_t)l * 256 * 256, nb1 + l * 256,
            ng1 + l * 256, nbt1 + l * 256,
            nW2 + (size_t)l * 256 * 128, nb2 + l * 128,
            ng2 + l * 128, nbt2 + l * 128);
    }
    k_dec<<<NN, 128>>>(dec_W1, dec_b1, dec_W2, dec_b2, (float*)d_out);
}

// round 3
// speedup vs baseline: 1.1562x; 1.1562x over previous
#include <cuda_runtime.h>
#include <cuda_bf16.h>
#include <cstdint>

#define NN 50000
#define NE 600000
#define HD 128

#define EDGE_SMEM 167936   // (64*260 + 64*132 + 2*32*264)*4
#define NODE_SMEM 200704   // (2*64*260 + 2*32*264)*4
#define P_SMEM    101376   // (64*132 + 2*32*264)*4

// ---------------- device scratch (no allocations allowed) ----------------
__device__ float g_h[NN * HD];
__device__ float g_ea[(size_t)NE * HD];
__device__ float g_P1[(size_t)NN * 256];
__device__ float g_P2[(size_t)NN * 256];
__device__ float g_agg[NN * HD];
__device__ float g_inv[NN];
__device__ int   g_cnt[NN];
__device__ int   g_row[NE];
__device__ int   g_col[NE];
__device__ int   g_is64;

// ---------------- helpers ----------------
__device__ __forceinline__ float gelu(float x) { return x * normcdff(x); }

__device__ __forceinline__ void split(float x, uint32_t& hi, uint32_t& lo) {
    asm("cvt.rna.tf32.f32 %0, %1;" : "=r"(hi) : "f"(x));
    float r = x - __uint_as_float(hi);
    asm("cvt.rna.tf32.f32 %0, %1;" : "=r"(lo) : "f"(r));
}

__device__ __forceinline__ void mma_t(float4& d, const uint32_t* a,
                                      uint32_t b0, uint32_t b1) {
    asm("mma.sync.aligned.m16n8k8.row.col.f32.tf32.tf32.f32 "
        "{%0,%1,%2,%3},{%4,%5,%6,%7},{%8,%9},{%0,%1,%2,%3};"
        : "+f"(d.x), "+f"(d.y), "+f"(d.z), "+f"(d.w)
        : "r"(a[0]), "r"(a[1]), "r"(a[2]), "r"(a[3]), "r"(b0), "r"(b1));
}

// Stage a 32 x (NQ*4) weight chunk into hi/lo tf32 smem buffers (ld 264).
template <int NQ>
__device__ __forceinline__ void stageW(float* sWh, float* sWl,
                                       const float* __restrict__ W, int ldW, int tid) {
    for (int t = tid; t < 32 * NQ; t += 256) {
        int r = t / NQ, q = t % NQ;
        float4 w = *(const float4*)&W[(size_t)r * ldW + q * 4];
        uint32_t h0, l0, h1, l1, h2, l2, h3, l3;
        split(w.x, h0, l0); split(w.y, h1, l1);
        split(w.z, h2, l2); split(w.w, h3, l3);
        float4 hv = make_float4(__uint_as_float(h0), __uint_as_float(h1),
                                __uint_as_float(h2), __uint_as_float(h3));
        float4 lv = make_float4(__uint_as_float(l0), __uint_as_float(l1),
                                __uint_as_float(l2), __uint_as_float(l3));
        *(float4*)&sWh[r * 264 + q * 4] = hv;
        *(float4*)&sWl[r * 264 + q * 4] = lv;
    }
}

// One 32-k chunk of 3xTF32 mma. Warp tile: M=32 (rows aRow..aRow+31), N=NT*8.
template <int NT>
__device__ __forceinline__ void mma_chunk(const float* sA, int ldA, int aRow, int kOff,
                                          const float* sWh, const float* sWl, int cb,
                                          float4 (&acc)[2][NT], int lane) {
    int g = lane >> 2, tig = lane & 3;
#pragma unroll
    for (int ks = 0; ks < 4; ks++) {
        int k0 = ks * 8;
        uint32_t ah[2][4], al[2][4];
#pragma unroll
        for (int mt = 0; mt < 2; mt++) {
            int r0 = aRow + mt * 16 + g;
            float x0 = sA[r0 * ldA + kOff + k0 + tig];
            float x1 = sA[(r0 + 8) * ldA + kOff + k0 + tig];
            float x2 = sA[r0 * ldA + kOff + k0 + tig + 4];
            float x3 = sA[(r0 + 8) * ldA + kOff + k0 + tig + 4];
            split(x0, ah[mt][0], al[mt][0]);
            split(x1, ah[mt][1], al[mt][1]);
            split(x2, ah[mt][2], al[mt][2]);
            split(x3, ah[mt][3], al[mt][3]);
        }
#pragma unroll
        for (int nt = 0; nt < NT; nt++) {
            int wi = (k0 + tig) * 264 + cb + nt * 8 + g;
            uint32_t bh0 = __float_as_uint(sWh[wi]);
            uint32_t bh1 = __float_as_uint(sWh[wi + 4 * 264]);
            uint32_t bl0 = __float_as_uint(sWl[wi]);
            uint32_t bl1 = __float_as_uint(sWl[wi + 4 * 264]);
#pragma unroll
            for (int mt = 0; mt < 2; mt++) {
                mma_t(acc[mt][nt], al[mt], bh0, bh1);
                mma_t(acc[mt][nt], ah[mt], bl0, bl1);
                mma_t(acc[mt][nt], ah[mt], bh0, bh1);
            }
        }
    }
}

// ---------------- index canonicalization ----------------
__global__ void k_detect(const void* __restrict__ ei) {
    if (threadIdx.x == 0) {
        const long long* p = (const long long*)ei;
        int ok = 1;
        for (int i = 0; i < 64; i++) {
            long long v = p[i];
            if (v < 0 || v >= NN) { ok = 0; break; }
        }
        g_is64 = ok;
    }
}

__global__ void k_convert(const void* __restrict__ ei) {
    int e = blockIdx.x * blockDim.x + threadIdx.x;
    if (e >= NE) return;
    if (g_is64) {
        const long long* p = (const long long*)ei;
        g_row[e] = (int)p[e];
        g_col[e] = (int)p[NE + e];
    } else {
        const int* p = (const int*)ei;
        g_row[e] = p[e];
        g_col[e] = p[NE + e];
    }
}

__global__ void k_deg() {
    int e = blockIdx.x * blockDim.x + threadIdx.x;
    if (e < NE) atomicAdd(&g_cnt[g_col[e]], 1);
}

__global__ void k_inv() {
    int n = blockIdx.x * blockDim.x + threadIdx.x;
    if (n < NN) {
        g_inv[n] = 1.0f / fmaxf((float)g_cnt[n], 1.0f);
        g_cnt[n] = 0;
    }
}

// ---------------- encoders ----------------
__device__ __forceinline__ float warpsum(float s) {
#pragma unroll
    for (int o = 16; o; o >>= 1) s += __shfl_xor_sync(0xffffffffu, s, o);
    return s;
}

__global__ void k_enc(const float* __restrict__ x, const float* __restrict__ W,
                      const float* __restrict__ b, const float* __restrict__ g,
                      const float* __restrict__ be) {
    int n = blockIdx.x, j = threadIdx.x;
    __shared__ float sx[8];
    __shared__ float red[8];
    if (j < 7) sx[j] = x[n * 7 + j];
    __syncthreads();
    float a = b[j];
#pragma unroll
    for (int k = 0; k < 7; k++) a = fmaf(sx[k], W[k * HD + j], a);
    int w = j >> 5, lane = j & 31;
    float s = warpsum(a);
    if (lane == 0) red[w] = s;
    __syncthreads();
    float m = (red[0] + red[1] + red[2] + red[3]) * (1.0f / HD);
    float d = a - m;
    float q = warpsum(d * d);
    if (lane == 0) red[4 + w] = q;
    __syncthreads();
    float var = (red[4] + red[5] + red[6] + red[7]) * (1.0f / HD);
    float t = d * rsqrtf(var + 1e-5f) * g[j] + be[j];
    g_h[(size_t)n * HD + j] = gelu(t);
}

__global__ void k_ee(const float* __restrict__ ea, const float* __restrict__ W,
                     const float* __restrict__ b) {
    int e = blockIdx.x, j = threadIdx.x;
    __shared__ float sa[8];
    if (j < 8) sa[j] = ea[e * 8 + j];
    __syncthreads();
    float a = b[j];
#pragma unroll
    for (int k = 0; k < 8; k++) a = fmaf(sa[k], W[k * HD + j], a);
    g_ea[(size_t)e * HD + j] = a;
}

// ---------------- node projections P1 = h@W1a + b1, P2 = h@W1b ----------------
__global__ void __launch_bounds__(256, 1) k_P(const float* __restrict__ W,
                                              const float* __restrict__ b1) {
    extern __shared__ float sm[];
    float* sA  = sm;                 // 64 x 132
    float* sWh = sA + 64 * 132;      // 32 x 264
    float* sWl = sWh + 32 * 264;     // 32 x 264
    int tid = threadIdx.x, lane = tid & 31, wid = tid >> 5;
    int g = lane >> 2, tig = lane & 3;
    int base = blockIdx.x * 64;
    int part = blockIdx.y;
    const float* Wp = W + (size_t)part * 128 * 256;
    float* out = part ? g_P2 : g_P1;

    for (int t = tid; t < 64 * 32; t += 256) {
        int i = t >> 5, q = t & 31;
        int n = base + i;
        float4 v = (n < NN) ? ((const float4*)g_h)[(size_t)n * 32 + q]
                            : make_float4(0, 0, 0, 0);
        *(float4*)&sA[i * 132 + q * 4] = v;
    }
    __syncthreads();

    int rowg = (wid >> 2) * 32;
    int cb1 = (wid & 3) * 64;
    float4 acc[2][8];
#pragma unroll
    for (int mt = 0; mt < 2; mt++)
#pragma unroll
        for (int nt = 0; nt < 8; nt++) acc[mt][nt] = make_float4(0, 0, 0, 0);
    for (int kc = 0; kc < 4; kc++) {
        __syncthreads();
        stageW<64>(sWh, sWl, Wp + (size_t)kc * 32 * 256, 256, tid);
        __syncthreads();
        mma_chunk<8>(sA, 132, rowg, kc * 32, sWh, sWl, cb1, acc, lane);
    }
#pragma unroll
    for (int mt = 0; mt < 2; mt++) {
        int r0 = base + rowg + mt * 16 + g;
#pragma unroll
        for (int nt = 0; nt < 8; nt++) {
            int C = cb1 + nt * 8 + 2 * tig;
            float bx = part ? 0.f : __ldg(&b1[C]);
            float by = part ? 0.f : __ldg(&b1[C + 1]);
            if (r0 < NN)
                *(float2*)&out[(size_t)r0 * 256 + C] =
                    make_float2(acc[mt][nt].x + bx, acc[mt][nt].y + by);
            if (r0 + 8 < NN)
                *(float2*)&out[(size_t)(r0 + 8) * 256 + C] =
                    make_float2(acc[mt][nt].z + bx, acc[mt][nt].w + by);
        }
    }
}

// ---------------- fused edge update ----------------
__global__ void __launch_bounds__(256, 1) k_edge(
    const float* __restrict__ W1c, const float* __restrict__ g1,
    const float* __restrict__ bt1, const float* __restrict__ W2,
    const float* __restrict__ b2, const float* __restrict__ g2,
    const float* __restrict__ bt2) {
    extern __shared__ float sm[];
    float* sPre = sm;                 // 64 x 260
    float* sEa  = sPre + 64 * 260;    // 64 x 132
    float* sWh  = sEa + 64 * 132;     // 32 x 264
    float* sWl  = sWh + 32 * 264;     // 32 x 264
    __shared__ int sRow[64], sCol[64];
    __shared__ __align__(16) float sRed[512];
    __shared__ float sP[896];
    int tid = threadIdx.x, lane = tid & 31, wid = tid >> 5;
    int g = lane >> 2, tig = lane & 3;
    int base = blockIdx.x * 64;

    if (tid < 64) { sRow[tid] = g_row[base + tid]; sCol[tid] = g_col[base + tid]; }
    for (int t = tid; t < 896; t += 256)
        sP[t] = (t < 256) ? g1[t] : (t < 512) ? bt1[t - 256]
              : (t < 640) ? b2[t - 512] : (t < 768) ? g2[t - 640] : bt2[t - 768];
    __syncthreads();

    for (int t = tid; t < 64 * 64; t += 256) {
        int e = t >> 6, q = t & 63;
        float4 v1 = ((const float4*)g_P1)[(size_t)sRow[e] * 64 + q];
        float4 v2 = ((const float4*)g_P2)[(size_t)sCol[e] * 64 + q];
        v1.x += v2.x; v1.y += v2.y; v1.z += v2.z; v1.w += v2.w;
        *(float4*)&sPre[e * 260 + q * 4] = v1;
    }
    for (int t = tid; t < 64 * 32; t += 256) {
        int e = t >> 5, q = t & 31;
        *(float4*)&sEa[e * 132 + q * 4] = ((const float4*)g_ea)[(size_t)(base + e) * 32 + q];
    }
    __syncthreads();

    int rowg = (wid >> 2) * 32;
    int cb1 = (wid & 3) * 64;
    int wcol = wid & 3;

    // GEMM1: acc = pre + ea @ W1c   (M=64, N=256, K=128)
    float4 acc[2][8];
#pragma unroll
    for (int mt = 0; mt < 2; mt++) {
        int r0 = rowg + mt * 16 + g;
#pragma unroll
        for (int nt = 0; nt < 8; nt++) {
            int C = cb1 + nt * 8 + 2 * tig;
            float2 u = *(const float2*)&sPre[r0 * 260 + C];
            float2 v = *(const float2*)&sPre[(r0 + 8) * 260 + C];
            acc[mt][nt] = make_float4(u.x, u.y, v.x, v.y);
        }
    }
    for (int kc = 0; kc < 4; kc++) {
        __syncthreads();
        stageW<64>(sWh, sWl, W1c + (size_t)kc * 32 * 256, 256, tid);
        __syncthreads();
        mma_chunk<8>(sEa, 132, rowg, kc * 32, sWh, sWl, cb1, acc, lane);
    }

    // LN(256) + GELU -> t into sPre
    {
        float p[2][2] = {{0, 0}, {0, 0}};
#pragma unroll
        for (int mt = 0; mt < 2; mt++)
#pragma unroll
            for (int nt = 0; nt < 8; nt++) {
                p[mt][0] += acc[mt][nt].x + acc[mt][nt].y;
                p[mt][1] += acc[mt][nt].z + acc[mt][nt].w;
            }
#pragma unroll
        for (int mt = 0; mt < 2; mt++)
#pragma unroll
            for (int h = 0; h < 2; h++) {
                p[mt][h] += __shfl_xor_sync(0xffffffffu, p[mt][h], 1);
                p[mt][h] += __shfl_xor_sync(0xffffffffu, p[mt][h], 2);
            }
        if (tig == 0)
#pragma unroll
            for (int mt = 0; mt < 2; mt++)
#pragma unroll
                for (int h = 0; h < 2; h++)
                    sRed[(rowg + mt * 16 + h * 8 + g) * 4 + wcol] = p[mt][h];
        __syncthreads();
        float m[2][2];
#pragma unroll
        for (int mt = 0; mt < 2; mt++)
#pragma unroll
            for (int h = 0; h < 2; h++) {
                float4 s = *(const float4*)&sRed[(rowg + mt * 16 + h * 8 + g) * 4];
                m[mt][h] = (s.x + s.y + s.z + s.w) * (1.0f / 256);
            }
        float q[2][2] = {{0, 0}, {0, 0}};
#pragma unroll
        for (int mt = 0; mt < 2; mt++)
#pragma unroll
            for (int nt = 0; nt < 8; nt++) {
                float dx = acc[mt][nt].x - m[mt][0], dy = acc[mt][nt].y - m[mt][0];
                float dz = acc[mt][nt].z - m[mt][1], dw = acc[mt][nt].w - m[mt][1];
                q[mt][0] += dx * dx + dy * dy;
                q[mt][1] += dz * dz + dw * dw;
            }
#pragma unroll
        for (int mt = 0; mt < 2; mt++)
#pragma unroll
            for (int h = 0; h < 2; h++) {
                q[mt][h] += __shfl_xor_sync(0xffffffffu, q[mt][h], 1);
                q[mt][h] += __shfl_xor_sync(0xffffffffu, q[mt][h], 2);
            }
        if (tig == 0)
#pragma unroll
            for (int mt = 0; mt < 2; mt++)
#pragma unroll
                for (int h = 0; h < 2; h++)
                    sRed[256 + (rowg + mt * 16 + h * 8 + g) * 4 + wcol] = q[mt][h];
        __syncthreads();
        float rn[2][2];
#pragma unroll
        for (int mt = 0; mt < 2; mt++)
#pragma unroll
            for (int h = 0; h < 2; h++) {
                float4 s = *(const float4*)&sRed[256 + (rowg + mt * 16 + h * 8 + g) * 4];
                rn[mt][h] = rsqrtf((s.x + s.y + s.z + s.w) * (1.0f / 256) + 1e-5f);
            }
#pragma unroll
        for (int mt = 0; mt < 2; mt++) {
            int r0 = rowg + mt * 16 + g;
#pragma unroll
            for (int nt = 0; nt < 8; nt++) {
                int C = cb1 + nt * 8 + 2 * tig;
                float gx = sP[C], gy = sP[C + 1];
                float bx = sP[256 + C], by = sP[256 + C + 1];
                float tx = gelu((acc[mt][nt].x - m[mt][0]) * rn[mt][0] * gx + bx);
                float ty = gelu((acc[mt][nt].y - m[mt][0]) * rn[mt][0] * gy + by);
                float tz = gelu((acc[mt][nt].z - m[mt][1]) * rn[mt][1] * gx + bx);
                float tw = gelu((acc[mt][nt].w - m[mt][1]) * rn[mt][1] * gy + by);
                *(float2*)&sPre[r0 * 260 + C] = make_float2(tx, ty);
                *(float2*)&sPre[(r0 + 8) * 260 + C] = make_float2(tz, tw);
            }
        }
    }

    // GEMM2: t @ W2  (M=64, N=128, K=256)
    int cb2 = (wid & 3) * 32;
    float4 acc2[2][4];
#pragma unroll
    for (int mt = 0; mt < 2; mt++)
#pragma unroll
        for (int nt = 0; nt < 4; nt++) acc2[mt][nt] = make_float4(0, 0, 0, 0);
    for (int kc = 0; kc < 8; kc++) {
        __syncthreads();
        stageW<32>(sWh, sWl, W2 + (size_t)kc * 32 * 128, 128, tid);
        __syncthreads();
        mma_chunk<4>(sPre, 260, rowg, kc * 32, sWh, sWl, cb2, acc2, lane);
    }

    // + b2, LN(128), residual, store + scatter
    {
#pragma unroll
        for (int mt = 0; mt < 2; mt++)
#pragma unroll
            for (int nt = 0; nt < 4; nt++) {
                int C = cb2 + nt * 8 + 2 * tig;
                acc2[mt][nt].x += sP[512 + C]; acc2[mt][nt].y += sP[512 + C + 1];
                acc2[mt][nt].z += sP[512 + C]; acc2[mt][nt].w += sP[512 + C + 1];
            }
        float p[2][2] = {{0, 0}, {0, 0}};
#pragma unroll
        for (int mt = 0; mt < 2; mt++)
#pragma unroll
            for (int nt = 0; nt < 4; nt++) {
                p[mt][0] += acc2[mt][nt].x + acc2[mt][nt].y;
                p[mt][1] += acc2[mt][nt].z + acc2[mt][nt].w;
            }
#pragma unroll
        for (int mt = 0; mt < 2; mt++)
#pragma unroll
            for (int h = 0; h < 2; h++) {
                p[mt][h] += __shfl_xor_sync(0xffffffffu, p[mt][h], 1);
                p[mt][h] += __shfl_xor_sync(0xffffffffu, p[mt][h], 2);
            }
        if (tig == 0)
#pragma unroll
            for (int mt = 0; mt < 2; mt++)
#pragma unroll
                for (int h = 0; h < 2; h++)
                    sRed[(rowg + mt * 16 + h * 8 + g) * 4 + wcol] = p[mt][h];
        __syncthreads();
        float m[2][2];
#pragma unroll
        for (int mt = 0; mt < 2; mt++)
#pragma unroll
            for (int h = 0; h < 2; h++) {
                float4 s = *(const float4*)&sRed[(rowg + mt * 16 + h * 8 + g) * 4];
                m[mt][h] = (s.x + s.y + s.z + s.w) * (1.0f / 128);
            }
        float q[2][2] = {{0, 0}, {0, 0}};
#pragma unroll
        for (int mt = 0; mt < 2; mt++)
#pragma unroll
            for (int nt = 0; nt < 4; nt++) {
                float dx = acc2[mt][nt].x - m[mt][0], dy = acc2[mt][nt].y - m[mt][0];
                float dz = acc2[mt][nt].z - m[mt][1], dw = acc2[mt][nt].w - m[mt][1];
                q[mt][0] += dx * dx + dy * dy;
                q[mt][1] += dz * dz + dw * dw;
            }
#pragma unroll
        for (int mt = 0; mt < 2; mt++)
#pragma unroll
            for (int h = 0; h < 2; h++) {
                q[mt][h] += __shfl_xor_sync(0xffffffffu, q[mt][h], 1);
                q[mt][h] += __shfl_xor_sync(0xffffffffu, q[mt][h], 2);
            }
        if (tig == 0)
#pragma unroll
            for (int mt = 0; mt < 2; mt++)
#pragma unroll
                for (int h = 0; h < 2; h++)
                    sRed[256 + (rowg + mt * 16 + h * 8 + g) * 4 + wcol] = q[mt][h];
        __syncthreads();
        float rn[2][2];
#pragma unroll
        for (int mt = 0; mt < 2; mt++)
#pragma unroll
            for (int h = 0; h < 2; h++) {
                float4 s = *(const float4*)&sRed[256 + (rowg + mt * 16 + h * 8 + g) * 4];
                rn[mt][h] = rsqrtf((s.x + s.y + s.z + s.w) * (1.0f / 128) + 1e-5f);
            }
#pragma unroll
        for (int mt = 0; mt < 2; mt++) {
            int r0 = rowg + mt * 16 + g;
            int r1 = r0 + 8;
#pragma unroll
            for (int nt = 0; nt < 4; nt++) {
                int C = cb2 + nt * 8 + 2 * tig;
                float gx = sP[640 + C], gy = sP[640 + C + 1];
                float bx = sP[768 + C], by = sP[768 + C + 1];
                float ox = sEa[r0 * 132 + C]     + (acc2[mt][nt].x - m[mt][0]) * rn[mt][0] * gx + bx;
                float oy = sEa[r0 * 132 + C + 1] + (acc2[mt][nt].y - m[mt][0]) * rn[mt][0] * gy + by;
                float oz = sEa[r1 * 132 + C]     + (acc2[mt][nt].z - m[mt][1]) * rn[mt][1] * gx + bx;
                float ow = sEa[r1 * 132 + C + 1] + (acc2[mt][nt].w - m[mt][1]) * rn[mt][1] * gy + by;
                *(float2*)&g_ea[(size_t)(base + r0) * HD + C] = make_float2(ox, oy);
                *(float2*)&g_ea[(size_t)(base + r1) * HD + C] = make_float2(oz, ow);
                float* a0 = &g_agg[(size_t)sCol[r0] * HD + C];
                float* a1 = &g_agg[(size_t)sCol[r1] * HD + C];
                atomicAdd(a0, ox); atomicAdd(a0 + 1, oy);
                atomicAdd(a1, oz); atomicAdd(a1 + 1, ow);
            }
        }
    }
}

// ---------------- fused node update ----------------
__global__ void __launch_bounds__(256, 1) k_node(
    const float* __restrict__ W1, const float* __restrict__ b1,
    const float* __restrict__ g1, const float* __restrict__ bt1,
    const float* __restrict__ W2, const float* __restrict__ b2,
    const float* __restrict__ g2, const float* __restrict__ bt2) {
    extern __shared__ float sm[];
    float* sA  = sm;                 // 64 x 260
    float* sT  = sA + 64 * 260;      // 64 x 260
    float* sWh = sT + 64 * 260;      // 32 x 264
    float* sWl = sWh + 32 * 264;     // 32 x 264
    __shared__ __align__(16) float sRed[512];
    __shared__ float sP[1152];
    int tid = threadIdx.x, lane = tid & 31, wid = tid >> 5;
    int g = lane >> 2, tig = lane & 3;
    int base = blockIdx.x * 64;

    for (int t = tid; t < 1152; t += 256)
        sP[t] = (t < 256) ? b1[t] : (t < 512) ? g1[t - 256] : (t < 768) ? bt1[t - 512]
              : (t < 896) ? b2[t - 768] : (t < 1024) ? g2[t - 896] : bt2[t - 1024];

    for (int t = tid; t < 64 * 32; t += 256) {
        int i = t >> 5, q = t & 31;
        int n = base + i;
        float4 v = (n < NN) ? ((const float4*)g_h)[(size_t)n * 32 + q]
                            : make_float4(0, 0, 0, 0);
        *(float4*)&sA[i * 260 + q * 4] = v;
    }
    for (int t = tid; t < 64 * 32; t += 256) {
        int i = t >> 5, q = t & 31;
        int n = base + i;
        float4 v = make_float4(0, 0, 0, 0);
        if (n < NN) {
            float4* ap = (float4*)&g_agg[(size_t)n * HD + q * 4];
            v = *ap;
            float iv = g_inv[n];
            v.x *= iv; v.y *= iv; v.z *= iv; v.w *= iv;
            *ap = make_float4(0, 0, 0, 0);
        }
        *(float4*)&sA[i * 260 + 128 + q * 4] = v;
    }
    __syncthreads();

    int rowg = (wid >> 2) * 32;
    int cb1 = (wid & 3) * 64;
    int wcol = wid & 3;

    // GEMM1 (M=64, N=256, K=256), acc init = b1
    float4 acc[2][8];
#pragma unroll
    for (int mt = 0; mt < 2; mt++)
#pragma unroll
        for (int nt = 0; nt < 8; nt++) {
            int C = cb1 + nt * 8 + 2 * tig;
            acc[mt][nt] = make_float4(sP[C], sP[C + 1], sP[C], sP[C + 1]);
        }
    for (int kc = 0; kc < 8; kc++) {
        __syncthreads();
        stageW<64>(sWh, sWl, W1 + (size_t)kc * 32 * 256, 256, tid);
        __syncthreads();
        mma_chunk<8>(sA, 260, rowg, kc * 32, sWh, sWl, cb1, acc, lane);
    }

    // LN(256) + GELU -> sT
    {
        float p[2][2] = {{0, 0}, {0, 0}};
#pragma unroll
        for (int mt = 0; mt < 2; mt++)
#pragma unroll
            for (int nt = 0; nt < 8; nt++) {
                p[mt][0] += acc[mt][nt].x + acc[mt][nt].y;
                p[mt][1] += acc[mt][nt].z + acc[mt][nt].w;
            }
#pragma unroll
        for (int mt = 0; mt < 2; mt++)
#pragma unroll
            for (int h = 0; h < 2; h++) {
                p[mt][h] += __shfl_xor_sync(0xffffffffu, p[mt][h], 1);
                p[mt][h] += __shfl_xor_sync(0xffffffffu, p[mt][h], 2);
            }
        if (tig == 0)
#pragma unroll
            for (int mt = 0; mt < 2; mt++)
#pragma unroll
                for (int h = 0; h < 2; h++)
                    sRed[(rowg + mt * 16 + h * 8 + g) * 4 + wcol] = p[mt][h];
        __syncthreads();
        float m[2][2];
#pragma unroll
        for (int mt = 0; mt < 2; mt++)
#pragma unroll
            for (int h = 0; h < 2; h++) {
                float4 s = *(const float4*)&sRed[(rowg + mt * 16 + h * 8 + g) * 4];
                m[mt][h] = (s.x + s.y + s.z + s.w) * (1.0f / 256);
            }
        float q[2][2] = {{0, 0}, {0, 0}};
#pragma unroll
        for (int mt = 0; mt < 2; mt++)
#pragma unroll
            for (int nt = 0; nt < 8; nt++) {
                float dx = acc[mt][nt].x - m[mt][0], dy = acc[mt][nt].y - m[mt][0];
                float dz = acc[mt][nt].z - m[mt][1], dw = acc[mt][nt].w - m[mt][1];
                q[mt][0] += dx * dx + dy * dy;
                q[mt][1] += dz * dz + dw * dw;
            }
#pragma unroll
        for (int mt = 0; mt < 2; mt++)
#pragma unroll
            for (int h = 0; h < 2; h++) {
                q[mt][h] += __shfl_xor_sync(0xffffffffu, q[mt][h], 1);
                q[mt][h] += __shfl_xor_sync(0xffffffffu, q[mt][h], 2);
            }
        if (tig == 0)
#pragma unroll
            for (int mt = 0; mt < 2; mt++)
#pragma unroll
                for (int h = 0; h < 2; h++)
                    sRed[256 + (rowg + mt * 16 + h * 8 + g) * 4 + wcol] = q[mt][h];
        __syncthreads();
        float rn[2][2];
#pragma unroll
        for (int mt = 0; mt < 2; mt++)
#pragma unroll
            for (int h = 0; h < 2; h++) {
                float4 s = *(const float4*)&sRed[256 + (rowg + mt * 16 + h * 8 + g) * 4];
                rn[mt][h] = rsqrtf((s.x + s.y + s.z + s.w) * (1.0f / 256) + 1e-5f);
            }
#pragma unroll
        for (int mt = 0; mt < 2; mt++) {
            int r0 = rowg + mt * 16 + g;
#pragma unroll
            for (int nt = 0; nt < 8; nt++) {
                int C = cb1 + nt * 8 + 2 * tig;
                float gx = sP[256 + C], gy = sP[256 + C + 1];
                float bx = sP[512 + C], by = sP[512 + C + 1];
                float tx = gelu((acc[mt][nt].x - m[mt][0]) * rn[mt][0] * gx + bx);
                float ty = gelu((acc[mt][nt].y - m[mt][0]) * rn[mt][0] * gy + by);
                float tz = gelu((acc[mt][nt].z - m[mt][1]) * rn[mt][1] * gx + bx);
                float tw = gelu((acc[mt][nt].w - m[mt][1]) * rn[mt][1] * gy + by);
                *(float2*)&sT[r0 * 260 + C] = make_float2(tx, ty);
                *(float2*)&sT[(r0 + 8) * 260 + C] = make_float2(tz, tw);
            }
        }
    }

    // GEMM2 (M=64, N=128, K=256)
    int cb2 = (wid & 3) * 32;
    float4 acc2[2][4];
#pragma unroll
    for (int mt = 0; mt < 2; mt++)
#pragma unroll
        for (int nt = 0; nt < 4; nt++) acc2[mt][nt] = make_float4(0, 0, 0, 0);
    for (int kc = 0; kc < 8; kc++) {
        __syncthreads();
        stageW<32>(sWh, sWl, W2 + (size_t)kc * 32 * 128, 128, tid);
        __syncthreads();
        mma_chunk<4>(sT, 260, rowg, kc * 32, sWh, sWl, cb2, acc2, lane);
    }

    // + b2, LN(128), residual from g_h, store h
    {
#pragma unroll
        for (int mt = 0; mt < 2; mt++)
#pragma unroll
            for (int nt = 0; nt < 4; nt++) {
                int C = cb2 + nt * 8 + 2 * tig;
                acc2[mt][nt].x += sP[768 + C]; acc2[mt][nt].y += sP[768 + C + 1];
                acc2[mt][nt].z += sP[768 + C]; acc2[mt][nt].w += sP[768 + C + 1];
            }
        float p[2][2] = {{0, 0}, {0, 0}};
#pragma unroll
        for (int mt = 0; mt < 2; mt++)
#pragma unroll
            for (int nt = 0; nt < 4; nt++) {
                p[mt][0] += acc2[mt][nt].x + acc2[mt][nt].y;
                p[mt][1] += acc2[mt][nt].z + acc2[mt][nt].w;
            }
#pragma unroll
        for (int mt = 0; mt < 2; mt++)
#pragma unroll
            for (int h = 0; h < 2; h++) {
                p[mt][h] += __shfl_xor_sync(0xffffffffu, p[mt][h], 1);
                p[mt][h] += __shfl_xor_sync(0xffffffffu, p[mt][h], 2);
            }
        if (tig == 0)
#pragma unroll
            for (int mt = 0; mt < 2; mt++)
#pragma unroll
                for (int h = 0; h < 2; h++)
                    sRed[(rowg + mt * 16 + h * 8 + g) * 4 + wcol] = p[mt][h];
        __syncthreads();
        float m[2][2];
#pragma unroll
        for (int mt = 0; mt < 2; mt++)
#pragma unroll
            for (int h = 0; h < 2; h++) {
                float4 s = *(const float4*)&sRed[(rowg + mt * 16 + h * 8 + g) * 4];
                m[mt][h] = (s.x + s.y + s.z + s.w) * (1.0f / 128);
            }
        float q[2][2] = {{0, 0}, {0, 0}};
#pragma unroll
        for (int mt = 0; mt < 2; mt++)
#pragma unroll
            for (int nt = 0; nt < 4; nt++) {
                float dx = acc2[mt][nt].x - m[mt][0], dy = acc2[mt][nt].y - m[mt][0];
                float dz = acc2[mt][nt].z - m[mt][1], dw = acc2[mt][nt].w - m[mt][1];
                q[mt][0] += dx * dx + dy * dy;
                q[mt][1] += dz * dz + dw * dw;
            }
#pragma unroll
        for (int mt = 0; mt < 2; mt++)
#pragma unroll
            for (int h = 0; h < 2; h++) {
                q[mt][h] += __shfl_xor_sync(0xffffffffu, q[mt][h], 1);
                q[mt][h] += __shfl_xor_sync(0xffffffffu, q[mt][h], 2);
            }
        if (tig == 0)
#pragma unroll
            for (int mt = 0; mt < 2; mt++)
#pragma unroll
                for (int h = 0; h < 2; h++)
                    sRed[256 + (rowg + mt * 16 + h * 8 + g) * 4 + wcol] = q[mt][h];
        __syncthreads();
        float rn[2][2];
#pragma unroll
        for (int mt = 0; mt < 2; mt++)
#pragma unroll
            for (int h = 0; h < 2; h++) {
                float4 s = *(const float4*)&sRed[256 + (rowg + mt * 16 + h * 8 + g) * 4];
                rn[mt][h] = rsqrtf((s.x + s.y + s.z + s.w) * (1.0f / 128) + 1e-5f);
            }
#pragma unroll
        for (int mt = 0; mt < 2; mt++) {
            int r0 = rowg + mt * 16 + g;
            int r1 = r0 + 8;
            int n0 = base + r0, n1 = base + r1;
#pragma unroll
            for (int nt = 0; nt < 4; nt++) {
                int C = cb2 + nt * 8 + 2 * tig;
                float gx = sP[896 + C], gy = sP[896 + C + 1];
                float bx = sP[1024 + C], by = sP[1024 + C + 1];
                if (n0 < NN) {
                    float2 hr = *(const float2*)&g_h[(size_t)n0 * HD + C];
                    float ox = hr.x + (acc2[mt][nt].x - m[mt][0]) * rn[mt][0] * gx + bx;
                    float oy = hr.y + (acc2[mt][nt].y - m[mt][0]) * rn[mt][0] * gy + by;
                    *(float2*)&g_h[(size_t)n0 * HD + C] = make_float2(ox, oy);
                }
                if (n1 < NN) {
                    float2 hr = *(const float2*)&g_h[(size_t)n1 * HD + C];
                    float oz = hr.x + (acc2[mt][nt].z - m[mt][1]) * rn[mt][1] * gx + bx;
                    float ow = hr.y + (acc2[mt][nt].w - m[mt][1]) * rn[mt][1] * gy + by;
                    *(float2*)&g_h[(size_t)n1 * HD + C] = make_float2(oz, ow);
                }
            }
        }
    }
}

// ---------------- decoder ----------------
__global__ void k_dec(const float* __restrict__ W1, const float* __restrict__ b1,
                      const float* __restrict__ W2, const float* __restrict__ b2,
                      float* __restrict__ out) {
    int n = blockIdx.x, j = threadIdx.x;
    __shared__ float sh[128];
    __shared__ float st[128];
    sh[j] = g_h[(size_t)n * HD + j];
    __syncthreads();
    float a = b1[j];
#pragma unroll 8
    for (int k = 0; k < 128; k++) a = fmaf(sh[k], W1[k * HD + j], a);
    st[j] = gelu(a);
    __syncthreads();
    int w = j >> 5, lane = j & 31;
    float s = 0;
#pragma unroll
    for (int k = lane; k < 128; k += 32) s = fmaf(st[k], W2[k * 4 + w], s);
    s = warpsum(s);
    if (lane == 0) out[(size_t)n * 4 + w] = s + b2[w];
}

// ---------------- launch ----------------
extern "C" void kernel_launch(void* const* d_in, const int* in_sizes, int n_in,
                              void* d_out, int out_size) {
    (void)in_sizes; (void)n_in; (void)out_size;
    const float* x       = (const float*)d_in[0];
    const void*  ei      = d_in[1];
    const float* eattr   = (const float*)d_in[2];
    const float* enc_W   = (const float*)d_in[3];
    const float* enc_b   = (const float*)d_in[4];
    const float* enc_g   = (const float*)d_in[5];
    const float* enc_bt  = (const float*)d_in[6];
    const float* ee_W    = (const float*)d_in[7];
    const float* ee_b    = (const float*)d_in[8];
    const float* eW1     = (const float*)d_in[9];
    const float* eb1     = (const float*)d_in[10];
    const float* eg1     = (const float*)d_in[11];
    const float* ebt1    = (const float*)d_in[12];
    const float* eW2     = (const float*)d_in[13];
    const float* eb2     = (const float*)d_in[14];
    const float* eg2     = (const float*)d_in[15];
    const float* ebt2    = (const float*)d_in[16];
    const float* nW1     = (const float*)d_in[17];
    const float* nb1     = (const float*)d_in[18];
    const float* ng1     = (const float*)d_in[19];
    const float* nbt1    = (const float*)d_in[20];
    const float* nW2     = (const float*)d_in[21];
    const float* nb2     = (const float*)d_in[22];
    const float* ng2     = (const float*)d_in[23];
    const float* nbt2    = (const float*)d_in[24];
    const float* dec_W1  = (const float*)d_in[25];
    const float* dec_b1  = (const float*)d_in[26];
    const float* dec_W2  = (const float*)d_in[27];
    const float* dec_b2  = (const float*)d_in[28];

    cudaFuncSetAttribute(k_edge, cudaFuncAttributeMaxDynamicSharedMemorySize, EDGE_SMEM);
    cudaFuncSetAttribute(k_node, cudaFuncAttributeMaxDynamicSharedMemorySize, NODE_SMEM);
    cudaFuncSetAttribute(k_P,    cudaFuncAttributeMaxDynamicSharedMemorySize, P_SMEM);

    k_detect<<<1, 32>>>(ei);
    k_convert<<<(NE + 255) / 256, 256>>>(ei);
    k_deg<<<(NE + 255) / 256, 256>>>();
    k_inv<<<(NN + 255) / 256, 256>>>();
    k_enc<<<NN, 128>>>(x, enc_W, enc_b, enc_g, enc_bt);
    k_ee<<<NE, 128>>>(eattr, ee_W, ee_b);

    const int nodeBlocks = (NN + 63) / 64;  // 782
    for (int l = 0; l < 10; l++) {
        const float* W1l = eW1 + (size_t)l * 384 * 256;
        k_P<<<dim3(nodeBlocks, 2), 256, P_SMEM>>>(W1l, eb1 + l * 256);
        k_edge<<<NE / 64, 256, EDGE_SMEM>>>(
            W1l + 256 * 256, eg1 + l * 256, ebt1 + l * 256,
            eW2 + (size_t)l * 256 * 128, eb2 + l * 128,
            eg2 + l * 128, ebt2 + l * 128);
        k_node<<<nodeBlocks, 256, NODE_SMEM>>>(
            nW1 + (size_t)l * 256 * 256, nb1 + l * 256,
            ng1 + l * 256, nbt1 + l * 256,
            nW2 + (size_t)l * 256 * 128, nb2 + l * 128,
            ng2 + l * 128, nbt2 + l * 128);
    }
    k_dec<<<NN, 128>>>(dec_W1, dec_b1, dec_W2, dec_b2, (float*)d_out);
}

// round 4
// speedup vs baseline: 1.5400x; 1.3320x over previous
#include <cuda_runtime.h>
#include <cuda_bf16.h>
#include <cstdint>

#define NN 50000
#define NE 600000
#define HD 128

#define EDGE_SMEM 169472   // (64*264 + 64*132 + 2*64*68 + 2*16*260)*4
#define NODE_SMEM 100864   // (2*64*132 + 2*16*260)*4
#define P_SMEM    68096    // (2*64*68 + 2*16*260)*4

// packed-weight plane offsets in g_Wb (uint32 units)
#define EW1_OFF 0          // per layer 2*192*256 = 98304
#define EW2_OFF 983040     // per layer 2*128*128 = 32768
#define NW1_OFF 1310720    // per layer 2*128*256 = 65536
#define NW2_OFF 1966080    // per layer 32768
#define WB_TOTAL 2293760

// ---------------- device scratch ----------------
__device__ float g_h[NN * HD];
__device__ float g_ea[(size_t)NE * HD];
__device__ float g_P1[(size_t)NN * 256];
__device__ float g_P2[(size_t)NN * 256];
__device__ float g_agg[NN * HD];
__device__ float g_inv[NN];
__device__ int   g_cnt[NN];
__device__ int   g_row[NE];
__device__ int   g_col[NE];
__device__ int   g_is64;
__device__ uint32_t g_Wb[WB_TOTAL];

// ---------------- helpers ----------------
__device__ __forceinline__ float gelu(float x) { return x * normcdff(x); }

// pack two fp32 into bf16x2: a -> low half (even k), b -> high half (odd k)
__device__ __forceinline__ uint32_t pack2(float a, float b) {
    uint32_t r;
    asm("cvt.rn.bf16x2.f32 %0, %1, %2;" : "=r"(r) : "f"(b), "f"(a));
    return r;
}

// split (a,b) into hi bf16x2 + lo (residual) bf16x2
__device__ __forceinline__ void split2(float a, float b, uint32_t& hi, uint32_t& lo) {
    hi = pack2(a, b);
    float ra = a - __uint_as_float(hi << 16);
    float rb = b - __uint_as_float(hi & 0xffff0000u);
    lo = pack2(ra, rb);
}

__device__ __forceinline__ void mma_bf(float4& d, const uint32_t* a,
                                       uint32_t b0, uint32_t b1) {
    asm("mma.sync.aligned.m16n8k16.row.col.f32.bf16.bf16.f32 "
        "{%0,%1,%2,%3},{%4,%5,%6,%7},{%8,%9},{%0,%1,%2,%3};"
        : "+f"(d.x), "+f"(d.y), "+f"(d.z), "+f"(d.w)
        : "r"(a[0]), "r"(a[1]), "r"(a[2]), "r"(a[3]), "r"(b0), "r"(b1));
}

// Copy 16 packed-k rows x N cols of hi/lo weight planes into smem (pure copy).
__device__ __forceinline__ void stage16(uint32_t* sWh, uint32_t* sWl,
                                        const uint32_t* __restrict__ hiP,
                                        const uint32_t* __restrict__ loP,
                                        int kpBase, int N, int ld, int tid) {
    int q4n = N >> 2;
    for (int t = tid; t < 16 * q4n; t += 256) {
        int r = t / q4n, q = t - r * q4n;
        *(uint4*)&sWh[r * ld + q * 4] = *(const uint4*)&hiP[(size_t)(kpBase + r) * N + q * 4];
        *(uint4*)&sWl[r * ld + q * 4] = *(const uint4*)&loP[(size_t)(kpBase + r) * N + q * 4];
    }
}

// One k32 chunk (two m16n8k16 steps), 3-term bf16-split MMA.
// Warp tile M=32 (rows aRow..+31), N = NT*8 (cols cb..).
template <int NT>
__device__ __forceinline__ void mma_chunk_bf(
    const uint32_t* sAh, const uint32_t* sAl, int ldA, int aRow, int kpOff,
    const uint32_t* sWh, const uint32_t* sWl, int ldW, int cb,
    float4 (&acc)[2][NT], int lane) {
    int g = lane >> 2, tig = lane & 3;
#pragma unroll
    for (int ks = 0; ks < 2; ks++) {
        int cbase = kpOff + ks * 8;
        uint32_t ah[2][4], al[2][4];
#pragma unroll
        for (int mt = 0; mt < 2; mt++) {
            int r0 = aRow + mt * 16 + g, r1 = r0 + 8;
            ah[mt][0] = sAh[r0 * ldA + cbase + tig];
            ah[mt][1] = sAh[r1 * ldA + cbase + tig];
            ah[mt][2] = sAh[r0 * ldA + cbase + tig + 4];
            ah[mt][3] = sAh[r1 * ldA + cbase + tig + 4];
            al[mt][0] = sAl[r0 * ldA + cbase + tig];
            al[mt][1] = sAl[r1 * ldA + cbase + tig];
            al[mt][2] = sAl[r0 * ldA + cbase + tig + 4];
            al[mt][3] = sAl[r1 * ldA + cbase + tig + 4];
        }
        int wr0 = ks * 8 + tig, wr1 = wr0 + 4;
#pragma unroll
        for (int nt = 0; nt < NT; nt++) {
            int n = cb + nt * 8 + g;
            uint32_t bh0 = sWh[wr0 * ldW + n], bh1 = sWh[wr1 * ldW + n];
            uint32_t bl0 = sWl[wr0 * ldW + n], bl1 = sWl[wr1 * ldW + n];
#pragma unroll
            for (int mt = 0; mt < 2; mt++) {
                mma_bf(acc[mt][nt], ah[mt], bh0, bh1);
                mma_bf(acc[mt][nt], ah[mt], bl0, bl1);
                mma_bf(acc[mt][nt], al[mt], bh0, bh1);
            }
        }
    }
}

// ---------------- weight pre-split kernel ----------------
__global__ void k_prep(const float* __restrict__ W, uint32_t* __restrict__ dst,
                       int KP, int N, int srcStride, int dstStride) {
    int l = blockIdx.y;
    int idx = blockIdx.x * blockDim.x + threadIdx.x;
    if (idx >= KP * N) return;
    int kp = idx / N, n = idx - kp * N;
    const float* Ws = W + (size_t)l * srcStride;
    float w0 = Ws[(size_t)(2 * kp) * N + n];
    float w1 = Ws[(size_t)(2 * kp + 1) * N + n];
    uint32_t hi, lo;
    split2(w0, w1, hi, lo);
    uint32_t* hp = dst + (size_t)l * dstStride;
    hp[(size_t)kp * N + n] = hi;
    hp[(size_t)KP * N + (size_t)kp * N + n] = lo;
}

// ---------------- index canonicalization ----------------
__global__ void k_detect(const void* __restrict__ ei) {
    if (threadIdx.x == 0) {
        const long long* p = (const long long*)ei;
        int ok = 1;
        for (int i = 0; i < 64; i++) {
            long long v = p[i];
            if (v < 0 || v >= NN) { ok = 0; break; }
        }
        g_is64 = ok;
    }
}

__global__ void k_convert(const void* __restrict__ ei) {
    int e = blockIdx.x * blockDim.x + threadIdx.x;
    if (e >= NE) return;
    if (g_is64) {
        const long long* p = (const long long*)ei;
        g_row[e] = (int)p[e];
        g_col[e] = (int)p[NE + e];
    } else {
        const int* p = (const int*)ei;
        g_row[e] = p[e];
        g_col[e] = p[NE + e];
    }
}

__global__ void k_deg() {
    int e = blockIdx.x * blockDim.x + threadIdx.x;
    if (e < NE) atomicAdd(&g_cnt[g_col[e]], 1);
}

__global__ void k_inv() {
    int n = blockIdx.x * blockDim.x + threadIdx.x;
    if (n < NN) {
        g_inv[n] = 1.0f / fmaxf((float)g_cnt[n], 1.0f);
        g_cnt[n] = 0;
    }
}

// ---------------- encoders ----------------
__device__ __forceinline__ float warpsum(float s) {
#pragma unroll
    for (int o = 16; o; o >>= 1) s += __shfl_xor_sync(0xffffffffu, s, o);
    return s;
}

__global__ void k_enc(const float* __restrict__ x, const float* __restrict__ W,
                      const float* __restrict__ b, const float* __restrict__ g,
                      const float* __restrict__ be) {
    int n = blockIdx.x, j = threadIdx.x;
    __shared__ float sx[8];
    __shared__ float red[8];
    if (j < 7) sx[j] = x[n * 7 + j];
    __syncthreads();
    float a = b[j];
#pragma unroll
    for (int k = 0; k < 7; k++) a = fmaf(sx[k], W[k * HD + j], a);
    int w = j >> 5, lane = j & 31;
    float s = warpsum(a);
    if (lane == 0) red[w] = s;
    __syncthreads();
    float m = (red[0] + red[1] + red[2] + red[3]) * (1.0f / HD);
    float d = a - m;
    float q = warpsum(d * d);
    if (lane == 0) red[4 + w] = q;
    __syncthreads();
    float var = (red[4] + red[5] + red[6] + red[7]) * (1.0f / HD);
    float t = d * rsqrtf(var + 1e-5f) * g[j] + be[j];
    g_h[(size_t)n * HD + j] = gelu(t);
}

__global__ void k_ee(const float* __restrict__ ea, const float* __restrict__ W,
                     const float* __restrict__ b) {
    int e = blockIdx.x, j = threadIdx.x;
    __shared__ float sa[8];
    if (j < 8) sa[j] = ea[e * 8 + j];
    __syncthreads();
    float a = b[j];
#pragma unroll
    for (int k = 0; k < 8; k++) a = fmaf(sa[k], W[k * HD + j], a);
    g_ea[(size_t)e * HD + j] = a;
}

// ---------------- node projections P1 = h@W1a + b1, P2 = h@W1b ----------------
__global__ void __launch_bounds__(256, 1) k_P(int w1Off, const float* __restrict__ b1) {
    extern __shared__ float sm[];
    uint32_t* hHi = (uint32_t*)sm;          // 64 x 68
    uint32_t* hLo = hHi + 64 * 68;
    uint32_t* sWh = hHi + 2 * 64 * 68;      // 16 x 260
    uint32_t* sWl = sWh + 16 * 260;
    int tid = threadIdx.x, lane = tid & 31, wid = tid >> 5;
    int g = lane >> 2, tig = lane & 3;
    int base = blockIdx.x * 64;
    int part = blockIdx.y;
    const uint32_t* hiP = g_Wb + w1Off;
    const uint32_t* loP = hiP + 49152;   // 192*256
    float* out = part ? g_P2 : g_P1;

    for (int t = tid; t < 64 * 32; t += 256) {
        int i = t >> 5, q = t & 31;
        int n = base + i;
        float4 v = (n < NN) ? ((const float4*)g_h)[(size_t)n * 32 + q]
                            : make_float4(0, 0, 0, 0);
        uint32_t h0, l0, h1, l1;
        split2(v.x, v.y, h0, l0);
        split2(v.z, v.w, h1, l1);
        hHi[i * 68 + 2 * q] = h0; hHi[i * 68 + 2 * q + 1] = h1;
        hLo[i * 68 + 2 * q] = l0; hLo[i * 68 + 2 * q + 1] = l1;
    }

    int rowg = (wid >> 2) * 32;
    int cb1 = (wid & 3) * 64;
    float4 acc[2][8];
#pragma unroll
    for (int mt = 0; mt < 2; mt++)
#pragma unroll
        for (int nt = 0; nt < 8; nt++) acc[mt][nt] = make_float4(0, 0, 0, 0);
    for (int kc = 0; kc < 4; kc++) {
        __syncthreads();
        stage16(sWh, sWl, hiP, loP, part * 64 + kc * 16, 256, 260, tid);
        __syncthreads();
        mma_chunk_bf<8>(hHi, hLo, 68, rowg, kc * 16, sWh, sWl, 260, cb1, acc, lane);
    }
#pragma unroll
    for (int mt = 0; mt < 2; mt++) {
        int r0 = base + rowg + mt * 16 + g;
#pragma unroll
        for (int nt = 0; nt < 8; nt++) {
            int C = cb1 + nt * 8 + 2 * tig;
            float bx = part ? 0.f : __ldg(&b1[C]);
            float by = part ? 0.f : __ldg(&b1[C + 1]);
            if (r0 < NN)
                *(float2*)&out[(size_t)r0 * 256 + C] =
                    make_float2(acc[mt][nt].x + bx, acc[mt][nt].y + by);
            if (r0 + 8 < NN)
                *(float2*)&out[(size_t)(r0 + 8) * 256 + C] =
                    make_float2(acc[mt][nt].z + bx, acc[mt][nt].w + by);
        }
    }
}

// ---------------- fused edge update ----------------
__global__ void __launch_bounds__(256, 1) k_edge(
    int w1Off, int w2Off,
    const float* __restrict__ g1, const float* __restrict__ bt1,
    const float* __restrict__ b2, const float* __restrict__ g2,
    const float* __restrict__ bt2) {
    extern __shared__ float sm[];
    float* sPre = sm;                          // 64 x 264 fp32
    float* sEa  = sm + 64 * 264;               // 64 x 132 fp32
    uint32_t* eHi = (uint32_t*)(sm + 64 * 264 + 64 * 132);  // 64 x 68
    uint32_t* eLo = eHi + 64 * 68;
    uint32_t* sWh = eHi + 2 * 64 * 68;         // 16 x 260 (GEMM1) / 16 x 132 (GEMM2)
    uint32_t* sWl = sWh + 16 * 260;
    uint32_t* tHi = (uint32_t*)sPre;           // alias: 64 x 132 packed
    uint32_t* tLo = tHi + 64 * 132;
    __shared__ int sRow[64], sCol[64];
    __shared__ __align__(16) float sRed[512];
    __shared__ float sP[896];
    int tid = threadIdx.x, lane = tid & 31, wid = tid >> 5;
    int g = lane >> 2, tig = lane & 3;
    int base = blockIdx.x * 64;
    const uint32_t* hi1 = g_Wb + w1Off;
    const uint32_t* lo1 = hi1 + 49152;
    const uint32_t* hi2 = g_Wb + w2Off;
    const uint32_t* lo2 = hi2 + 16384;

    if (tid < 64) { sRow[tid] = g_row[base + tid]; sCol[tid] = g_col[base + tid]; }
    for (int t = tid; t < 896; t += 256)
        sP[t] = (t < 256) ? g1[t] : (t < 512) ? bt1[t - 256]
              : (t < 640) ? b2[t - 512] : (t < 768) ? g2[t - 640] : bt2[t - 768];
    __syncthreads();

    for (int t = tid; t < 64 * 64; t += 256) {   // pre = P1[row] + P2[col]
        int e = t >> 6, q = t & 63;
        float4 v1 = ((const float4*)g_P1)[(size_t)sRow[e] * 64 + q];
        float4 v2 = ((const float4*)g_P2)[(size_t)sCol[e] * 64 + q];
        v1.x += v2.x; v1.y += v2.y; v1.z += v2.z; v1.w += v2.w;
        *(float4*)&sPre[e * 264 + q * 4] = v1;
    }
    for (int t = tid; t < 64 * 32; t += 256) {   // ea tile: fp32 + packed bf16
        int e = t >> 5, q = t & 31;
        float4 v = ((const float4*)g_ea)[(size_t)(base + e) * 32 + q];
        *(float4*)&sEa[e * 132 + q * 4] = v;
        uint32_t h0, l0, h1, l1;
        split2(v.x, v.y, h0, l0);
        split2(v.z, v.w, h1, l1);
        eHi[e * 68 + 2 * q] = h0; eHi[e * 68 + 2 * q + 1] = h1;
        eLo[e * 68 + 2 * q] = l0; eLo[e * 68 + 2 * q + 1] = l1;
    }
    __syncthreads();

    int rowg = (wid >> 2) * 32;
    int cb1 = (wid & 3) * 64;
    int wcol = wid & 3;

    // GEMM1: acc = pre + ea @ W1c   (M=64, N=256, K=128)
    float4 acc[2][8];
#pragma unroll
    for (int mt = 0; mt < 2; mt++) {
        int r0 = rowg + mt * 16 + g;
#pragma unroll
        for (int nt = 0; nt < 8; nt++) {
            int C = cb1 + nt * 8 + 2 * tig;
            float2 u = *(const float2*)&sPre[r0 * 264 + C];
            float2 v = *(const float2*)&sPre[(r0 + 8) * 264 + C];
            acc[mt][nt] = make_float4(u.x, u.y, v.x, v.y);
        }
    }
    for (int kc = 0; kc < 4; kc++) {
        __syncthreads();
        stage16(sWh, sWl, hi1, lo1, 128 + kc * 16, 256, 260, tid);
        __syncthreads();
        mma_chunk_bf<8>(eHi, eLo, 68, rowg, kc * 16, sWh, sWl, 260, cb1, acc, lane);
    }

    // LN(256) + GELU -> t (packed, aliased on sPre)
    {
        float p[2][2] = {{0, 0}, {0, 0}};
#pragma unroll
        for (int mt = 0; mt < 2; mt++)
#pragma unroll
            for (int nt = 0; nt < 8; nt++) {
                p[mt][0] += acc[mt][nt].x + acc[mt][nt].y;
                p[mt][1] += acc[mt][nt].z + acc[mt][nt].w;
            }
#pragma unroll
        for (int mt = 0; mt < 2; mt++)
#pragma unroll
            for (int h = 0; h < 2; h++) {
                p[mt][h] += __shfl_xor_sync(0xffffffffu, p[mt][h], 1);
                p[mt][h] += __shfl_xor_sync(0xffffffffu, p[mt][h], 2);
            }
        if (tig == 0)
#pragma unroll
            for (int mt = 0; mt < 2; mt++)
#pragma unroll
                for (int h = 0; h < 2; h++)
                    sRed[(rowg + mt * 16 + h * 8 + g) * 4 + wcol] = p[mt][h];
        __syncthreads();
        float m[2][2];
#pragma unroll
        for (int mt = 0; mt < 2; mt++)
#pragma unroll
            for (int h = 0; h < 2; h++) {
                float4 s = *(const float4*)&sRed[(rowg + mt * 16 + h * 8 + g) * 4];
                m[mt][h] = (s.x + s.y + s.z + s.w) * (1.0f / 256);
            }
        float q[2][2] = {{0, 0}, {0, 0}};
#pragma unroll
        for (int mt = 0; mt < 2; mt++)
#pragma unroll
            for (int nt = 0; nt < 8; nt++) {
                float dx = acc[mt][nt].x - m[mt][0], dy = acc[mt][nt].y - m[mt][0];
                float dz = acc[mt][nt].z - m[mt][1], dw = acc[mt][nt].w - m[mt][1];
                q[mt][0] += dx * dx + dy * dy;
                q[mt][1] += dz * dz + dw * dw;
            }
#pragma unroll
        for (int mt = 0; mt < 2; mt++)
#pragma unroll
            for (int h = 0; h < 2; h++) {
                q[mt][h] += __shfl_xor_sync(0xffffffffu, q[mt][h], 1);
                q[mt][h] += __shfl_xor_sync(0xffffffffu, q[mt][h], 2);
            }
        if (tig == 0)
#pragma unroll
            for (int mt = 0; mt < 2; mt++)
#pragma unroll
                for (int h = 0; h < 2; h++)
                    sRed[256 + (rowg + mt * 16 + h * 8 + g) * 4 + wcol] = q[mt][h];
        __syncthreads();
        float rn[2][2];
#pragma unroll
        for (int mt = 0; mt < 2; mt++)
#pragma unroll
            for (int h = 0; h < 2; h++) {
                float4 s = *(const float4*)&sRed[256 + (rowg + mt * 16 + h * 8 + g) * 4];
                rn[mt][h] = rsqrtf((s.x + s.y + s.z + s.w) * (1.0f / 256) + 1e-5f);
            }
#pragma unroll
        for (int mt = 0; mt < 2; mt++) {
            int r0 = rowg + mt * 16 + g;
#pragma unroll
            for (int nt = 0; nt < 8; nt++) {
                int C = cb1 + nt * 8 + 2 * tig;
                int cp = C >> 1;
                float gx = sP[C], gy = sP[C + 1];
                float bx = sP[256 + C], by = sP[256 + C + 1];
                float tx = gelu((acc[mt][nt].x - m[mt][0]) * rn[mt][0] * gx + bx);
                float ty = gelu((acc[mt][nt].y - m[mt][0]) * rn[mt][0] * gy + by);
                float tz = gelu((acc[mt][nt].z - m[mt][1]) * rn[mt][1] * gx + bx);
                float tw = gelu((acc[mt][nt].w - m[mt][1]) * rn[mt][1] * gy + by);
                uint32_t h0, l0, h1, l1;
                split2(tx, ty, h0, l0);
                split2(tz, tw, h1, l1);
                tHi[r0 * 132 + cp] = h0; tLo[r0 * 132 + cp] = l0;
                tHi[(r0 + 8) * 132 + cp] = h1; tLo[(r0 + 8) * 132 + cp] = l1;
            }
        }
    }

    // GEMM2: t @ W2  (M=64, N=128, K=256)
    int cb2 = (wid & 3) * 32;
    float4 acc2[2][4];
#pragma unroll
    for (int mt = 0; mt < 2; mt++)
#pragma unroll
        for (int nt = 0; nt < 4; nt++) acc2[mt][nt] = make_float4(0, 0, 0, 0);
    for (int kc = 0; kc < 8; kc++) {
        __syncthreads();
        stage16(sWh, sWl, hi2, lo2, kc * 16, 128, 132, tid);
        __syncthreads();
        mma_chunk_bf<4>(tHi, tLo, 132, rowg, kc * 16, sWh, sWl, 132, cb2, acc2, lane);
    }

    // + b2, LN(128), residual, store + scatter
    {
#pragma unroll
        for (int mt = 0; mt < 2; mt++)
#pragma unroll
            for (int nt = 0; nt < 4; nt++) {
                int C = cb2 + nt * 8 + 2 * tig;
                acc2[mt][nt].x += sP[512 + C]; acc2[mt][nt].y += sP[512 + C + 1];
                acc2[mt][nt].z += sP[512 + C]; acc2[mt][nt].w += sP[512 + C + 1];
            }
        float p[2][2] = {{0, 0}, {0, 0}};
#pragma unroll
        for (int mt = 0; mt < 2; mt++)
#pragma unroll
            for (int nt = 0; nt < 4; nt++) {
                p[mt][0] += acc2[mt][nt].x + acc2[mt][nt].y;
                p[mt][1] += acc2[mt][nt].z + acc2[mt][nt].w;
            }
#pragma unroll
        for (int mt = 0; mt < 2; mt++)
#pragma unroll
            for (int h = 0; h < 2; h++) {
                p[mt][h] += __shfl_xor_sync(0xffffffffu, p[mt][h], 1);
                p[mt][h] += __shfl_xor_sync(0xffffffffu, p[mt][h], 2);
            }
        if (tig == 0)
#pragma unroll
            for (int mt = 0; mt < 2; mt++)
#pragma unroll
                for (int h = 0; h < 2; h++)
                    sRed[(rowg + mt * 16 + h * 8 + g) * 4 + wcol] = p[mt][h];
        __syncthreads();
        float m[2][2];
#pragma unroll
        for (int mt = 0; mt < 2; mt++)
#pragma unroll
            for (int h = 0; h < 2; h++) {
                float4 s = *(const float4*)&sRed[(rowg + mt * 16 + h * 8 + g) * 4];
                m[mt][h] = (s.x + s.y + s.z + s.w) * (1.0f / 128);
            }
        float q[2][2] = {{0, 0}, {0, 0}};
#pragma unroll
        for (int mt = 0; mt < 2; mt++)
#pragma unroll
            for (int nt = 0; nt < 4; nt++) {
                float dx = acc2[mt][nt].x - m[mt][0], dy = acc2[mt][nt].y - m[mt][0];
                float dz = acc2[mt][nt].z - m[mt][1], dw = acc2[mt][nt].w - m[mt][1];
                q[mt][0] += dx * dx + dy * dy;
                q[mt][1] += dz * dz + dw * dw;
            }
#pragma unroll
        for (int mt = 0; mt < 2; mt++)
#pragma unroll
            for (int h = 0; h < 2; h++) {
                q[mt][h] += __shfl_xor_sync(0xffffffffu, q[mt][h], 1);
                q[mt][h] += __shfl_xor_sync(0xffffffffu, q[mt][h], 2);
            }
        if (tig == 0)
#pragma unroll
            for (int mt = 0; mt < 2; mt++)
#pragma unroll
                for (int h = 0; h < 2; h++)
                    sRed[256 + (rowg + mt * 16 + h * 8 + g) * 4 + wcol] = q[mt][h];
        __syncthreads();
        float rn[2][2];
#pragma unroll
        for (int mt = 0; mt < 2; mt++)
#pragma unroll
            for (int h = 0; h < 2; h++) {
                float4 s = *(const float4*)&sRed[256 + (rowg + mt * 16 + h * 8 + g) * 4];
                rn[mt][h] = rsqrtf((s.x + s.y + s.z + s.w) * (1.0f / 128) + 1e-5f);
            }
#pragma unroll
        for (int mt = 0; mt < 2; mt++) {
            int r0 = rowg + mt * 16 + g;
            int r1 = r0 + 8;
#pragma unroll
            for (int nt = 0; nt < 4; nt++) {
                int C = cb2 + nt * 8 + 2 * tig;
                float gx = sP[640 + C], gy = sP[640 + C + 1];
                float bx = sP[768 + C], by = sP[768 + C + 1];
                float ox = sEa[r0 * 132 + C]     + (acc2[mt][nt].x - m[mt][0]) * rn[mt][0] * gx + bx;
                float oy = sEa[r0 * 132 + C + 1] + (acc2[mt][nt].y - m[mt][0]) * rn[mt][0] * gy + by;
                float oz = sEa[r1 * 132 + C]     + (acc2[mt][nt].z - m[mt][1]) * rn[mt][1] * gx + bx;
                float ow = sEa[r1 * 132 + C + 1] + (acc2[mt][nt].w - m[mt][1]) * rn[mt][1] * gy + by;
                *(float2*)&g_ea[(size_t)(base + r0) * HD + C] = make_float2(ox, oy);
                *(float2*)&g_ea[(size_t)(base + r1) * HD + C] = make_float2(oz, ow);
                float* a0 = &g_agg[(size_t)sCol[r0] * HD + C];
                float* a1 = &g_agg[(size_t)sCol[r1] * HD + C];
                asm volatile("red.global.add.v2.f32 [%0], {%1,%2};"
                             :: "l"(a0), "f"(ox), "f"(oy) : "memory");
                asm volatile("red.global.add.v2.f32 [%0], {%1,%2};"
                             :: "l"(a1), "f"(oz), "f"(ow) : "memory");
            }
        }
    }
}

// ---------------- fused node update ----------------
__global__ void __launch_bounds__(256, 1) k_node(
    int w1Off, int w2Off,
    const float* __restrict__ b1, const float* __restrict__ g1,
    const float* __restrict__ bt1, const float* __restrict__ b2,
    const float* __restrict__ g2, const float* __restrict__ bt2) {
    extern __shared__ float sm[];
    uint32_t* aHi = (uint32_t*)sm;            // 64 x 132 packed (K=256)
    uint32_t* aLo = aHi + 64 * 132;
    uint32_t* sWh = aHi + 2 * 64 * 132;       // 16 x 260
    uint32_t* sWl = sWh + 16 * 260;
    uint32_t* tHi = aHi;                      // alias after GEMM1
    uint32_t* tLo = aLo;
    __shared__ __align__(16) float sRed[512];
    __shared__ float sP[1152];
    int tid = threadIdx.x, lane = tid & 31, wid = tid >> 5;
    int g = lane >> 2, tig = lane & 3;
    int base = blockIdx.x * 64;
    const uint32_t* hi1 = g_Wb + w1Off;
    const uint32_t* lo1 = hi1 + 32768;
    const uint32_t* hi2 = g_Wb + w2Off;
    const uint32_t* lo2 = hi2 + 16384;

    for (int t = tid; t < 1152; t += 256)
        sP[t] = (t < 256) ? b1[t] : (t < 512) ? g1[t - 256] : (t < 768) ? bt1[t - 512]
              : (t < 896) ? b2[t - 768] : (t < 1024) ? g2[t - 896] : bt2[t - 1024];

    for (int t = tid; t < 64 * 32; t += 256) {   // h -> packed cols 0..63
        int i = t >> 5, q = t & 31;
        int n = base + i;
        float4 v = (n < NN) ? ((const float4*)g_h)[(size_t)n * 32 + q]
                            : make_float4(0, 0, 0, 0);
        uint32_t h0, l0, h1, l1;
        split2(v.x, v.y, h0, l0);
        split2(v.z, v.w, h1, l1);
        aHi[i * 132 + 2 * q] = h0; aHi[i * 132 + 2 * q + 1] = h1;
        aLo[i * 132 + 2 * q] = l0; aLo[i * 132 + 2 * q + 1] = l1;
    }
    for (int t = tid; t < 64 * 32; t += 256) {   // agg*inv -> packed cols 64..127
        int i = t >> 5, q = t & 31;
        int n = base + i;
        float4 v = make_float4(0, 0, 0, 0);
        if (n < NN) {
            float4* ap = (float4*)&g_agg[(size_t)n * HD + q * 4];
            v = *ap;
            float iv = g_inv[n];
            v.x *= iv; v.y *= iv; v.z *= iv; v.w *= iv;
            *ap = make_float4(0, 0, 0, 0);
        }
        uint32_t h0, l0, h1, l1;
        split2(v.x, v.y, h0, l0);
        split2(v.z, v.w, h1, l1);
        aHi[i * 132 + 64 + 2 * q] = h0; aHi[i * 132 + 64 + 2 * q + 1] = h1;
        aLo[i * 132 + 64 + 2 * q] = l0; aLo[i * 132 + 64 + 2 * q + 1] = l1;
    }
    __syncthreads();

    int rowg = (wid >> 2) * 32;
    int cb1 = (wid & 3) * 64;
    int wcol = wid & 3;

    // GEMM1 (M=64, N=256, K=256), acc init = b1
    float4 acc[2][8];
#pragma unroll
    for (int mt = 0; mt < 2; mt++)
#pragma unroll
        for (int nt = 0; nt < 8; nt++) {
            int C = cb1 + nt * 8 + 2 * tig;
            acc[mt][nt] = make_float4(sP[C], sP[C + 1], sP[C], sP[C + 1]);
        }
    for (int kc = 0; kc < 8; kc++) {
        __syncthreads();
        stage16(sWh, sWl, hi1, lo1, kc * 16, 256, 260, tid);
        __syncthreads();
        mma_chunk_bf<8>(aHi, aLo, 132, rowg, kc * 16, sWh, sWl, 260, cb1, acc, lane);
    }

    // LN(256) + GELU -> t packed (aliased on A)
    {
        float p[2][2] = {{0, 0}, {0, 0}};
#pragma unroll
        for (int mt = 0; mt < 2; mt++)
#pragma unroll
            for (int nt = 0; nt < 8; nt++) {
                p[mt][0] += acc[mt][nt].x + acc[mt][nt].y;
                p[mt][1] += acc[mt][nt].z + acc[mt][nt].w;
            }
#pragma unroll
        for (int mt = 0; mt < 2; mt++)
#pragma unroll
            for (int h = 0; h < 2; h++) {
                p[mt][h] += __shfl_xor_sync(0xffffffffu, p[mt][h], 1);
                p[mt][h] += __shfl_xor_sync(0xffffffffu, p[mt][h], 2);
            }
        if (tig == 0)
#pragma unroll
            for (int mt = 0; mt < 2; mt++)
#pragma unroll
                for (int h = 0; h < 2; h++)
                    sRed[(rowg + mt * 16 + h * 8 + g) * 4 + wcol] = p[mt][h];
        __syncthreads();
        float m[2][2];
#pragma unroll
        for (int mt = 0; mt < 2; mt++)
#pragma unroll
            for (int h = 0; h < 2; h++) {
                float4 s = *(const float4*)&sRed[(rowg + mt * 16 + h * 8 + g) * 4];
                m[mt][h] = (s.x + s.y + s.z + s.w) * (1.0f / 256);
            }
        float q[2][2] = {{0, 0}, {0, 0}};
#pragma unroll
        for (int mt = 0; mt < 2; mt++)
#pragma unroll
            for (int nt = 0; nt < 8; nt++) {
                float dx = acc[mt][nt].x - m[mt][0], dy = acc[mt][nt].y - m[mt][0];
                float dz = acc[mt][nt].z - m[mt][1], dw = acc[mt][nt].w - m[mt][1];
                q[mt][0] += dx * dx + dy * dy;
                q[mt][1] += dz * dz + dw * dw;
            }
#pragma unroll
        for (int mt = 0; mt < 2; mt++)
#pragma unroll
            for (int h = 0; h < 2; h++) {
                q[mt][h] += __shfl_xor_sync(0xffffffffu, q[mt][h], 1);
                q[mt][h] += __shfl_xor_sync(0xffffffffu, q[mt][h], 2);
            }
        if (tig == 0)
#pragma unroll
            for (int mt = 0; mt < 2; mt++)
#pragma unroll
                for (int h = 0; h < 2; h++)
                    sRed[256 + (rowg + mt * 16 + h * 8 + g) * 4 + wcol] = q[mt][h];
        __syncthreads();
        float rn[2][2];
#pragma unroll
        for (int mt = 0; mt < 2; mt++)
#pragma unroll
            for (int h = 0; h < 2; h++) {
                float4 s = *(const float4*)&sRed[256 + (rowg + mt * 16 + h * 8 + g) * 4];
                rn[mt][h] = rsqrtf((s.x + s.y + s.z + s.w) * (1.0f / 256) + 1e-5f);
            }
#pragma unroll
        for (int mt = 0; mt < 2; mt++) {
            int r0 = rowg + mt * 16 + g;
#pragma unroll
            for (int nt = 0; nt < 8; nt++) {
                int C = cb1 + nt * 8 + 2 * tig;
                int cp = C >> 1;
                float gx = sP[256 + C], gy = sP[256 + C + 1];
                float bx = sP[512 + C], by = sP[512 + C + 1];
                float tx = gelu((acc[mt][nt].x - m[mt][0]) * rn[mt][0] * gx + bx);
                float ty = gelu((acc[mt][nt].y - m[mt][0]) * rn[mt][0] * gy + by);
                float tz = gelu((acc[mt][nt].z - m[mt][1]) * rn[mt][1] * gx + bx);
                float tw = gelu((acc[mt][nt].w - m[mt][1]) * rn[mt][1] * gy + by);
                uint32_t h0, l0, h1, l1;
                split2(tx, ty, h0, l0);
                split2(tz, tw, h1, l1);
                tHi[r0 * 132 + cp] = h0; tLo[r0 * 132 + cp] = l0;
                tHi[(r0 + 8) * 132 + cp] = h1; tLo[(r0 + 8) * 132 + cp] = l1;
            }
        }
    }

    // GEMM2 (M=64, N=128, K=256)
    int cb2 = (wid & 3) * 32;
    float4 acc2[2][4];
#pragma unroll
    for (int mt = 0; mt < 2; mt++)
#pragma unroll
        for (int nt = 0; nt < 4; nt++) acc2[mt][nt] = make_float4(0, 0, 0, 0);
    for (int kc = 0; kc < 8; kc++) {
        __syncthreads();
        stage16(sWh, sWl, hi2, lo2, kc * 16, 128, 132, tid);
        __syncthreads();
        mma_chunk_bf<4>(tHi, tLo, 132, rowg, kc * 16, sWh, sWl, 132, cb2, acc2, lane);
    }

    // + b2, LN(128), residual from g_h, store h
    {
#pragma unroll
        for (int mt = 0; mt < 2; mt++)
#pragma unroll
            for (int nt = 0; nt < 4; nt++) {
                int C = cb2 + nt * 8 + 2 * tig;
                acc2[mt][nt].x += sP[768 + C]; acc2[mt][nt].y += sP[768 + C + 1];
                acc2[mt][nt].z += sP[768 + C]; acc2[mt][nt].w += sP[768 + C + 1];
            }
        float p[2][2] = {{0, 0}, {0, 0}};
#pragma unroll
        for (int mt = 0; mt < 2; mt++)
#pragma unroll
            for (int nt = 0; nt < 4; nt++) {
                p[mt][0] += acc2[mt][nt].x + acc2[mt][nt].y;
                p[mt][1] += acc2[mt][nt].z + acc2[mt][nt].w;
            }
#pragma unroll
        for (int mt = 0; mt < 2; mt++)
#pragma unroll
            for (int h = 0; h < 2; h++) {
                p[mt][h] += __shfl_xor_sync(0xffffffffu, p[mt][h], 1);
                p[mt][h] += __shfl_xor_sync(0xffffffffu, p[mt][h], 2);
            }
        if (tig == 0)
#pragma unroll
            for (int mt = 0; mt < 2; mt++)
#pragma unroll
                for (int h = 0; h < 2; h++)
                    sRed[(rowg + mt * 16 + h * 8 + g) * 4 + wcol] = p[mt][h];
        __syncthreads();
        float m[2][2];
#pragma unroll
        for (int mt = 0; mt < 2; mt++)
#pragma unroll
            for (int h = 0; h < 2; h++) {
                float4 s = *(const float4*)&sRed[(rowg + mt * 16 + h * 8 + g) * 4];
                m[mt][h] = (s.x + s.y + s.z + s.w) * (1.0f / 128);
            }
        float q[2][2] = {{0, 0}, {0, 0}};
#pragma unroll
        for (int mt = 0; mt < 2; mt++)
#pragma unroll
            for (int nt = 0; nt < 4; nt++) {
                float dx = acc2[mt][nt].x - m[mt][0], dy = acc2[mt][nt].y - m[mt][0];
                float dz = acc2[mt][nt].z - m[mt][1], dw = acc2[mt][nt].w - m[mt][1];
                q[mt][0] += dx * dx + dy * dy;
                q[mt][1] += dz * dz + dw * dw;
            }
#pragma unroll
        for (int mt = 0; mt < 2; mt++)
#pragma unroll
            for (int h = 0; h < 2; h++) {
                q[mt][h] += __shfl_xor_sync(0xffffffffu, q[mt][h], 1);
                q[mt][h] += __shfl_xor_sync(0xffffffffu, q[mt][h], 2);
            }
        if (tig == 0)
#pragma unroll
            for (int mt = 0; mt < 2; mt++)
#pragma unroll
                for (int h = 0; h < 2; h++)
                    sRed[256 + (rowg + mt * 16 + h * 8 + g) * 4 + wcol] = q[mt][h];
        __syncthreads();
        float rn[2][2];
#pragma unroll
        for (int mt = 0; mt < 2; mt++)
#pragma unroll
            for (int h = 0; h < 2; h++) {
                float4 s = *(const float4*)&sRed[256 + (rowg + mt * 16 + h * 8 + g) * 4];
                rn[mt][h] = rsqrtf((s.x + s.y + s.z + s.w) * (1.0f / 128) + 1e-5f);
            }
#pragma unroll
        for (int mt = 0; mt < 2; mt++) {
            int r0 = rowg + mt * 16 + g;
            int r1 = r0 + 8;
            int n0 = base + r0, n1 = base + r1;
#pragma unroll
            for (int nt = 0; nt < 4; nt++) {
                int C = cb2 + nt * 8 + 2 * tig;
                float gx = sP[896 + C], gy = sP[896 + C + 1];
                float bx = sP[1024 + C], by = sP[1024 + C + 1];
                if (n0 < NN) {
                    float2 hr = *(const float2*)&g_h[(size_t)n0 * HD + C];
                    float ox = hr.x + (acc2[mt][nt].x - m[mt][0]) * rn[mt][0] * gx + bx;
                    float oy = hr.y + (acc2[mt][nt].y - m[mt][0]) * rn[mt][0] * gy + by;
                    *(float2*)&g_h[(size_t)n0 * HD + C] = make_float2(ox, oy);
                }
                if (n1 < NN) {
                    float2 hr = *(const float2*)&g_h[(size_t)n1 * HD + C];
                    float oz = hr.x + (acc2[mt][nt].z - m[mt][1]) * rn[mt][1] * gx + bx;
                    float ow = hr.y + (acc2[mt][nt].w - m[mt][1]) * rn[mt][1] * gy + by;
                    *(float2*)&g_h[(size_t)n1 * HD + C] = make_float2(oz, ow);
                }
            }
        }
    }
}

// ---------------- decoder ----------------
__global__ void k_dec(const float* __restrict__ W1, const float* __restrict__ b1,
                      const float* __restrict__ W2, const float* __restrict__ b2,
                      float* __restrict__ out) {
    int n = blockIdx.x, j = threadIdx.x;
    __shared__ float sh[128];
    __shared__ float st[128];
    sh[j] = g_h[(size_t)n * HD + j];
    __syncthreads();
    float a = b1[j];
#pragma unroll 8
    for (int k = 0; k < 128; k++) a = fmaf(sh[k], W1[k * HD + j], a);
    st[j] = gelu(a);
    __syncthreads();
    int w = j >> 5, lane = j & 31;
    float s = 0;
#pragma unroll
    for (int k = lane; k < 128; k += 32) s = fmaf(st[k], W2[k * 4 + w], s);
    s = warpsum(s);
    if (lane == 0) out[(size_t)n * 4 + w] = s + b2[w];
}

// ---------------- launch ----------------
extern "C" void kernel_launch(void* const* d_in, const int* in_sizes, int n_in,
                              void* d_out, int out_size) {
    (void)in_sizes; (void)n_in; (void)out_size;
    const float* x       = (const float*)d_in[0];
    const void*  ei      = d_in[1];
    const float* eattr   = (const float*)d_in[2];
    const float* enc_W   = (const float*)d_in[3];
    const float* enc_b   = (const float*)d_in[4];
    const float* enc_g   = (const float*)d_in[5];
    const float* enc_bt  = (const float*)d_in[6];
    const float* ee_W    = (const float*)d_in[7];
    const float* ee_b    = (const float*)d_in[8];
    const float* eW1     = (const float*)d_in[9];
    const float* eb1     = (const float*)d_in[10];
    const float* eg1     = (const float*)d_in[11];
    const float* ebt1    = (const float*)d_in[12];
    const float* eW2     = (const float*)d_in[13];
    const float* eb2     = (const float*)d_in[14];
    const float* eg2     = (const float*)d_in[15];
    const float* ebt2    = (const float*)d_in[16];
    const float* nW1     = (const float*)d_in[17];
    const float* nb1     = (const float*)d_in[18];
    const float* ng1     = (const float*)d_in[19];
    const float* nbt1    = (const float*)d_in[20];
    const float* nW2     = (const float*)d_in[21];
    const float* nb2     = (const float*)d_in[22];
    const float* ng2     = (const float*)d_in[23];
    const float* nbt2    = (const float*)d_in[24];
    const float* dec_W1  = (const float*)d_in[25];
    const float* dec_b1  = (const float*)d_in[26];
    const float* dec_W2  = (const float*)d_in[27];
    const float* dec_b2  = (const float*)d_in[28];

    cudaFuncSetAttribute(k_edge, cudaFuncAttributeMaxDynamicSharedMemorySize, EDGE_SMEM);
    cudaFuncSetAttribute(k_node, cudaFuncAttributeMaxDynamicSharedMemorySize, NODE_SMEM);
    cudaFuncSetAttribute(k_P,    cudaFuncAttributeMaxDynamicSharedMemorySize, P_SMEM);

    // pre-split weights into packed bf16 hi/lo planes (once per launch)
    {
        uint32_t* wb = nullptr;
        cudaGetSymbolAddress((void**)&wb, g_Wb);
        k_prep<<<dim3(192, 10), 256>>>(eW1, wb + EW1_OFF, 192, 256, 98304, 98304);
        k_prep<<<dim3(64, 10), 256>>>(eW2, wb + EW2_OFF, 128, 128, 32768, 32768);
        k_prep<<<dim3(128, 10), 256>>>(nW1, wb + NW1_OFF, 128, 256, 65536, 65536);
        k_prep<<<dim3(64, 10), 256>>>(nW2, wb + NW2_OFF, 128, 128, 32768, 32768);
    }

    k_detect<<<1, 32>>>(ei);
    k_convert<<<(NE + 255) / 256, 256>>>(ei);
    k_deg<<<(NE + 255) / 256, 256>>>();
    k_inv<<<(NN + 255) / 256, 256>>>();
    k_enc<<<NN, 128>>>(x, enc_W, enc_b, enc_g, enc_bt);
    k_ee<<<NE, 128>>>(eattr, ee_W, ee_b);

    const int nodeBlocks = (NN + 63) / 64;  // 782
    for (int l = 0; l < 10; l++) {
        k_P<<<dim3(nodeBlocks, 2), 256, P_SMEM>>>(EW1_OFF + l * 98304, eb1 + l * 256);
        k_edge<<<NE / 64, 256, EDGE_SMEM>>>(
            EW1_OFF + l * 98304, EW2_OFF + l * 32768,
            eg1 + l * 256, ebt1 + l * 256,
            eb2 + l * 128, eg2 + l * 128, ebt2 + l * 128);
        k_node<<<nodeBlocks, 256, NODE_SMEM>>>(
            NW1_OFF + l * 65536, NW2_OFF + l * 32768,
            nb1 + l * 256, ng1 + l * 256, nbt1 + l * 256,
            nb2 + l * 128, ng2 + l * 128, nbt2 + l * 128);
    }
    k_dec<<<NN, 128>>>(dec_W1, dec_b1, dec_W2, dec_b2, (float*)d_out);
}

// round 5
// speedup vs baseline: 2.2108x; 1.4356x over previous
#include <cuda_runtime.h>
#include <cuda_bf16.h>
#include <cstdint>

#define NN 50000
#define NE 600000
#define HD 128

// dynamic smem: union[ (eHi+eLo 64x68x2) | (tHi+tLo 64x132x2) ] + weights 2x16x260
#define EDGE_SMEM 100864   // (16896 + 8320) * 4
#define NODE_SMEM 100864
#define P_SMEM    68096    // (2*64*68 + 2*16*260)*4

// packed-weight plane offsets in g_Wb (uint32 units)
#define EW1_OFF 0          // per layer 2*192*256 = 98304
#define EW2_OFF 983040     // per layer 2*128*128 = 32768
#define NW1_OFF 1310720    // per layer 2*128*256 = 65536
#define NW2_OFF 1966080    // per layer 32768
#define WB_TOTAL 2293760

// ---------------- device scratch ----------------
__device__ float g_h[NN * HD];
__device__ float g_ea[(size_t)NE * HD];
__device__ float g_P1[(size_t)NN * 256];
__device__ float g_P2[(size_t)NN * 256];
__device__ float g_agg[NN * HD];
__device__ float g_inv[NN];
__device__ int   g_cnt[NN];
__device__ int   g_row[NE];
__device__ int   g_col[NE];
__device__ int   g_is64;
__device__ uint32_t g_Wb[WB_TOTAL];

// ---------------- helpers ----------------
__device__ __forceinline__ float gelu(float x) { return x * normcdff(x); }

__device__ __forceinline__ uint32_t pack2(float a, float b) {
    uint32_t r;
    asm("cvt.rn.bf16x2.f32 %0, %1, %2;" : "=r"(r) : "f"(b), "f"(a));
    return r;
}

__device__ __forceinline__ void split2(float a, float b, uint32_t& hi, uint32_t& lo) {
    hi = pack2(a, b);
    float ra = a - __uint_as_float(hi << 16);
    float rb = b - __uint_as_float(hi & 0xffff0000u);
    lo = pack2(ra, rb);
}

__device__ __forceinline__ void mma_bf(float4& d, const uint32_t* a,
                                       uint32_t b0, uint32_t b1) {
    asm("mma.sync.aligned.m16n8k16.row.col.f32.bf16.bf16.f32 "
        "{%0,%1,%2,%3},{%4,%5,%6,%7},{%8,%9},{%0,%1,%2,%3};"
        : "+f"(d.x), "+f"(d.y), "+f"(d.z), "+f"(d.w)
        : "r"(a[0]), "r"(a[1]), "r"(a[2]), "r"(a[3]), "r"(b0), "r"(b1));
}

// Copy 16 packed-k rows x N cols of hi/lo weight planes into smem (pure copy).
__device__ __forceinline__ void stage16(uint32_t* sWh, uint32_t* sWl,
                                        const uint32_t* __restrict__ hiP,
                                        const uint32_t* __restrict__ loP,
                                        int kpBase, int N, int ld, int tid) {
    int q4n = N >> 2;
    for (int t = tid; t < 16 * q4n; t += 256) {
        int r = t / q4n, q = t - r * q4n;
        *(uint4*)&sWh[r * ld + q * 4] = *(const uint4*)&hiP[(size_t)(kpBase + r) * N + q * 4];
        *(uint4*)&sWl[r * ld + q * 4] = *(const uint4*)&loP[(size_t)(kpBase + r) * N + q * 4];
    }
}

// One k32 chunk (two m16n8k16 steps), 3-term bf16-split MMA.
template <int NT>
__device__ __forceinline__ void mma_chunk_bf(
    const uint32_t* sAh, const uint32_t* sAl, int ldA, int aRow, int kpOff,
    const uint32_t* sWh, const uint32_t* sWl, int ldW, int cb,
    float4 (&acc)[2][NT], int lane) {
    int g = lane >> 2, tig = lane & 3;
#pragma unroll
    for (int ks = 0; ks < 2; ks++) {
        int cbase = kpOff + ks * 8;
        uint32_t ah[2][4], al[2][4];
#pragma unroll
        for (int mt = 0; mt < 2; mt++) {
            int r0 = aRow + mt * 16 + g, r1 = r0 + 8;
            ah[mt][0] = sAh[r0 * ldA + cbase + tig];
            ah[mt][1] = sAh[r1 * ldA + cbase + tig];
            ah[mt][2] = sAh[r0 * ldA + cbase + tig + 4];
            ah[mt][3] = sAh[r1 * ldA + cbase + tig + 4];
            al[mt][0] = sAl[r0 * ldA + cbase + tig];
            al[mt][1] = sAl[r1 * ldA + cbase + tig];
            al[mt][2] = sAl[r0 * ldA + cbase + tig + 4];
            al[mt][3] = sAl[r1 * ldA + cbase + tig + 4];
        }
        int wr0 = ks * 8 + tig, wr1 = wr0 + 4;
#pragma unroll
        for (int nt = 0; nt < NT; nt++) {
            int n = cb + nt * 8 + g;
            uint32_t bh0 = sWh[wr0 * ldW + n], bh1 = sWh[wr1 * ldW + n];
            uint32_t bl0 = sWl[wr0 * ldW + n], bl1 = sWl[wr1 * ldW + n];
#pragma unroll
            for (int mt = 0; mt < 2; mt++) {
                mma_bf(acc[mt][nt], ah[mt], bh0, bh1);
                mma_bf(acc[mt][nt], ah[mt], bl0, bl1);
                mma_bf(acc[mt][nt], al[mt], bh0, bh1);
            }
        }
    }
}

// ---------------- weight pre-split kernel ----------------
__global__ void k_prep(const float* __restrict__ W, uint32_t* __restrict__ dst,
                       int KP, int N, int srcStride, int dstStride) {
    int l = blockIdx.y;
    int idx = blockIdx.x * blockDim.x + threadIdx.x;
    if (idx >= KP * N) return;
    int kp = idx / N, n = idx - kp * N;
    const float* Ws = W + (size_t)l * srcStride;
    float w0 = Ws[(size_t)(2 * kp) * N + n];
    float w1 = Ws[(size_t)(2 * kp + 1) * N + n];
    uint32_t hi, lo;
    split2(w0, w1, hi, lo);
    uint32_t* hp = dst + (size_t)l * dstStride;
    hp[(size_t)kp * N + n] = hi;
    hp[(size_t)KP * N + (size_t)kp * N + n] = lo;
}

// ---------------- index canonicalization ----------------
__global__ void k_detect(const void* __restrict__ ei) {
    if (threadIdx.x == 0) {
        const long long* p = (const long long*)ei;
        int ok = 1;
        for (int i = 0; i < 64; i++) {
            long long v = p[i];
            if (v < 0 || v >= NN) { ok = 0; break; }
        }
        g_is64 = ok;
    }
}

__global__ void k_convert(const void* __restrict__ ei) {
    int e = blockIdx.x * blockDim.x + threadIdx.x;
    if (e >= NE) return;
    int r, c;
    if (g_is64) {
        const long long* p = (const long long*)ei;
        r = (int)p[e]; c = (int)p[NE + e];
    } else {
        const int* p = (const int*)ei;
        r = p[e]; c = p[NE + e];
    }
    g_row[e] = r;
    g_col[e] = c;
    atomicAdd(&g_cnt[c], 1);
}

__global__ void k_inv() {
    int n = blockIdx.x * blockDim.x + threadIdx.x;
    if (n < NN) {
        g_inv[n] = 1.0f / fmaxf((float)g_cnt[n], 1.0f);
        g_cnt[n] = 0;
    }
}

// ---------------- encoders ----------------
__device__ __forceinline__ float warpsum(float s) {
#pragma unroll
    for (int o = 16; o; o >>= 1) s += __shfl_xor_sync(0xffffffffu, s, o);
    return s;
}

__global__ void k_enc(const float* __restrict__ x, const float* __restrict__ W,
                      const float* __restrict__ b, const float* __restrict__ g,
                      const float* __restrict__ be) {
    int n = blockIdx.x, j = threadIdx.x;
    __shared__ float sx[8];
    __shared__ float red[8];
    if (j < 7) sx[j] = x[n * 7 + j];
    __syncthreads();
    float a = b[j];
#pragma unroll
    for (int k = 0; k < 7; k++) a = fmaf(sx[k], W[k * HD + j], a);
    int w = j >> 5, lane = j & 31;
    float s = warpsum(a);
    if (lane == 0) red[w] = s;
    __syncthreads();
    float m = (red[0] + red[1] + red[2] + red[3]) * (1.0f / HD);
    float d = a - m;
    float q = warpsum(d * d);
    if (lane == 0) red[4 + w] = q;
    __syncthreads();
    float var = (red[4] + red[5] + red[6] + red[7]) * (1.0f / HD);
    float t = d * rsqrtf(var + 1e-5f) * g[j] + be[j];
    g_h[(size_t)n * HD + j] = gelu(t);
}

__global__ void k_ee(const float* __restrict__ ea, const float* __restrict__ W,
                     const float* __restrict__ b) {
    int e = blockIdx.x, j = threadIdx.x;
    __shared__ float sa[8];
    if (j < 8) sa[j] = ea[e * 8 + j];
    __syncthreads();
    float a = b[j];
#pragma unroll
    for (int k = 0; k < 8; k++) a = fmaf(sa[k], W[k * HD + j], a);
    g_ea[(size_t)e * HD + j] = a;
}

// ---------------- node projections P1 = h@W1a + b1, P2 = h@W1b ----------------
__global__ void __launch_bounds__(256, 2) k_P(int w1Off, const float* __restrict__ b1) {
    extern __shared__ float sm[];
    uint32_t* hHi = (uint32_t*)sm;          // 64 x 68
    uint32_t* hLo = hHi + 64 * 68;
    uint32_t* sWh = hHi + 2 * 64 * 68;      // 16 x 260
    uint32_t* sWl = sWh + 16 * 260;
    int tid = threadIdx.x, lane = tid & 31, wid = tid >> 5;
    int g = lane >> 2, tig = lane & 3;
    int base = blockIdx.x * 64;
    int part = blockIdx.y;
    const uint32_t* hiP = g_Wb + w1Off;
    const uint32_t* loP = hiP + 49152;   // 192*256
    float* out = part ? g_P2 : g_P1;

    for (int t = tid; t < 64 * 32; t += 256) {
        int i = t >> 5, q = t & 31;
        int n = base + i;
        float4 v = (n < NN) ? ((const float4*)g_h)[(size_t)n * 32 + q]
                            : make_float4(0, 0, 0, 0);
        uint32_t h0, l0, h1, l1;
        split2(v.x, v.y, h0, l0);
        split2(v.z, v.w, h1, l1);
        hHi[i * 68 + 2 * q] = h0; hHi[i * 68 + 2 * q + 1] = h1;
        hLo[i * 68 + 2 * q] = l0; hLo[i * 68 + 2 * q + 1] = l1;
    }

    int rowg = (wid >> 2) * 32;
    int cb1 = (wid & 3) * 64;
    float4 acc[2][8];
#pragma unroll
    for (int mt = 0; mt < 2; mt++)
#pragma unroll
        for (int nt = 0; nt < 8; nt++) acc[mt][nt] = make_float4(0, 0, 0, 0);
    for (int kc = 0; kc < 4; kc++) {
        __syncthreads();
        stage16(sWh, sWl, hiP, loP, part * 64 + kc * 16, 256, 260, tid);
        __syncthreads();
        mma_chunk_bf<8>(hHi, hLo, 68, rowg, kc * 16, sWh, sWl, 260, cb1, acc, lane);
    }
#pragma unroll
    for (int mt = 0; mt < 2; mt++) {
        int r0 = base + rowg + mt * 16 + g;
#pragma unroll
        for (int nt = 0; nt < 8; nt++) {
            int C = cb1 + nt * 8 + 2 * tig;
            float bx = part ? 0.f : __ldg(&b1[C]);
            float by = part ? 0.f : __ldg(&b1[C + 1]);
            if (r0 < NN)
                *(float2*)&out[(size_t)r0 * 256 + C] =
                    make_float2(acc[mt][nt].x + bx, acc[mt][nt].y + by);
            if (r0 + 8 < NN)
                *(float2*)&out[(size_t)(r0 + 8) * 256 + C] =
                    make_float2(acc[mt][nt].z + bx, acc[mt][nt].w + by);
        }
    }
}

// ---------------- fused edge update ----------------
__global__ void __launch_bounds__(256, 2) k_edge(
    int w1Off, int w2Off,
    const float* __restrict__ g1, const float* __restrict__ bt1,
    const float* __restrict__ b2, const float* __restrict__ g2,
    const float* __restrict__ bt2) {
    extern __shared__ float sm[];
    uint32_t* buf = (uint32_t*)sm;
    uint32_t* eHi = buf;                 // 64 x 68 (GEMM1 A)
    uint32_t* eLo = buf + 64 * 68;
    uint32_t* tHi = buf;                 // 64 x 132 (GEMM2 A, aliases eHi/eLo)
    uint32_t* tLo = buf + 64 * 132;
    uint32_t* sWh = buf + 16896;         // 16 x 260
    uint32_t* sWl = sWh + 16 * 260;
    __shared__ int sRow[64], sCol[64];
    __shared__ __align__(16) float sRed[512];
    __shared__ float sP[896];
    int tid = threadIdx.x, lane = tid & 31, wid = tid >> 5;
    int g = lane >> 2, tig = lane & 3;
    int base = blockIdx.x * 64;
    const uint32_t* hi1 = g_Wb + w1Off;
    const uint32_t* lo1 = hi1 + 49152;
    const uint32_t* hi2 = g_Wb + w2Off;
    const uint32_t* lo2 = hi2 + 16384;

    if (tid < 64) { sRow[tid] = g_row[base + tid]; sCol[tid] = g_col[base + tid]; }
    for (int t = tid; t < 896; t += 256)
        sP[t] = (t < 256) ? g1[t] : (t < 512) ? bt1[t - 256]
              : (t < 640) ? b2[t - 512] : (t < 768) ? g2[t - 640] : bt2[t - 768];

    for (int t = tid; t < 64 * 32; t += 256) {   // ea tile -> packed bf16 planes
        int e = t >> 5, q = t & 31;
        float4 v = ((const float4*)g_ea)[(size_t)(base + e) * 32 + q];
        uint32_t h0, l0, h1, l1;
        split2(v.x, v.y, h0, l0);
        split2(v.z, v.w, h1, l1);
        eHi[e * 68 + 2 * q] = h0; eHi[e * 68 + 2 * q + 1] = h1;
        eLo[e * 68 + 2 * q] = l0; eLo[e * 68 + 2 * q + 1] = l1;
    }
    __syncthreads();

    int rowg = (wid >> 2) * 32;
    int cb1 = (wid & 3) * 64;
    int wcol = wid & 3;

    // GEMM1 acc init: per-fragment gather of P1[row] + P2[col]
    float4 acc[2][8];
#pragma unroll
    for (int mt = 0; mt < 2; mt++) {
        int r0 = rowg + mt * 16 + g, r1 = r0 + 8;
        const float* p1a = &g_P1[(size_t)sRow[r0] * 256];
        const float* p2a = &g_P2[(size_t)sCol[r0] * 256];
        const float* p1b = &g_P1[(size_t)sRow[r1] * 256];
        const float* p2b = &g_P2[(size_t)sCol[r1] * 256];
#pragma unroll
        for (int nt = 0; nt < 8; nt++) {
            int C = cb1 + nt * 8 + 2 * tig;
            float2 u1 = *(const float2*)&p1a[C];
            float2 u2 = *(const float2*)&p2a[C];
            float2 v1 = *(const float2*)&p1b[C];
            float2 v2 = *(const float2*)&p2b[C];
            acc[mt][nt] = make_float4(u1.x + u2.x, u1.y + u2.y,
                                      v1.x + v2.x, v1.y + v2.y);
        }
    }
    for (int kc = 0; kc < 4; kc++) {
        __syncthreads();
        stage16(sWh, sWl, hi1, lo1, 128 + kc * 16, 256, 260, tid);
        __syncthreads();
        mma_chunk_bf<8>(eHi, eLo, 68, rowg, kc * 16, sWh, sWl, 260, cb1, acc, lane);
    }

    // LN(256) + GELU -> t (packed, aliased over eHi/eLo)
    {
        float p[2][2] = {{0, 0}, {0, 0}};
#pragma unroll
        for (int mt = 0; mt < 2; mt++)
#pragma unroll
            for (int nt = 0; nt < 8; nt++) {
                p[mt][0] += acc[mt][nt].x + acc[mt][nt].y;
                p[mt][1] += acc[mt][nt].z + acc[mt][nt].w;
            }
#pragma unroll
        for (int mt = 0; mt < 2; mt++)
#pragma unroll
            for (int h = 0; h < 2; h++) {
                p[mt][h] += __shfl_xor_sync(0xffffffffu, p[mt][h], 1);
                p[mt][h] += __shfl_xor_sync(0xffffffffu, p[mt][h], 2);
            }
        if (tig == 0)
#pragma unroll
            for (int mt = 0; mt < 2; mt++)
#pragma unroll
                for (int h = 0; h < 2; h++)
                    sRed[(rowg + mt * 16 + h * 8 + g) * 4 + wcol] = p[mt][h];
        __syncthreads();
        float m[2][2];
#pragma unroll
        for (int mt = 0; mt < 2; mt++)
#pragma unroll
            for (int h = 0; h < 2; h++) {
                float4 s = *(const float4*)&sRed[(rowg + mt * 16 + h * 8 + g) * 4];
                m[mt][h] = (s.x + s.y + s.z + s.w) * (1.0f / 256);
            }
        float q[2][2] = {{0, 0}, {0, 0}};
#pragma unroll
        for (int mt = 0; mt < 2; mt++)
#pragma unroll
            for (int nt = 0; nt < 8; nt++) {
                float dx = acc[mt][nt].x - m[mt][0], dy = acc[mt][nt].y - m[mt][0];
                float dz = acc[mt][nt].z - m[mt][1], dw = acc[mt][nt].w - m[mt][1];
                q[mt][0] += dx * dx + dy * dy;
                q[mt][1] += dz * dz + dw * dw;
            }
#pragma unroll
        for (int mt = 0; mt < 2; mt++)
#pragma unroll
            for (int h = 0; h < 2; h++) {
                q[mt][h] += __shfl_xor_sync(0xffffffffu, q[mt][h], 1);
                q[mt][h] += __shfl_xor_sync(0xffffffffu, q[mt][h], 2);
            }
        if (tig == 0)
#pragma unroll
            for (int mt = 0; mt < 2; mt++)
#pragma unroll
                for (int h = 0; h < 2; h++)
                    sRed[256 + (rowg + mt * 16 + h * 8 + g) * 4 + wcol] = q[mt][h];
        __syncthreads();
        float rn[2][2];
#pragma unroll
        for (int mt = 0; mt < 2; mt++)
#pragma unroll
            for (int h = 0; h < 2; h++) {
                float4 s = *(const float4*)&sRed[256 + (rowg + mt * 16 + h * 8 + g) * 4];
                rn[mt][h] = rsqrtf((s.x + s.y + s.z + s.w) * (1.0f / 256) + 1e-5f);
            }
#pragma unroll
        for (int mt = 0; mt < 2; mt++) {
            int r0 = rowg + mt * 16 + g;
#pragma unroll
            for (int nt = 0; nt < 8; nt++) {
                int C = cb1 + nt * 8 + 2 * tig;
                int cp = C >> 1;
                float gx = sP[C], gy = sP[C + 1];
                float bx = sP[256 + C], by = sP[256 + C + 1];
                float tx = gelu((acc[mt][nt].x - m[mt][0]) * rn[mt][0] * gx + bx);
                float ty = gelu((acc[mt][nt].y - m[mt][0]) * rn[mt][0] * gy + by);
                float tz = gelu((acc[mt][nt].z - m[mt][1]) * rn[mt][1] * gx + bx);
                float tw = gelu((acc[mt][nt].w - m[mt][1]) * rn[mt][1] * gy + by);
                uint32_t h0, l0, h1, l1;
                split2(tx, ty, h0, l0);
                split2(tz, tw, h1, l1);
                tHi[r0 * 132 + cp] = h0; tLo[r0 * 132 + cp] = l0;
                tHi[(r0 + 8) * 132 + cp] = h1; tLo[(r0 + 8) * 132 + cp] = l1;
            }
        }
    }

    // GEMM2: t @ W2  (M=64, N=128, K=256)
    int cb2 = (wid & 3) * 32;
    float4 acc2[2][4];
#pragma unroll
    for (int mt = 0; mt < 2; mt++)
#pragma unroll
        for (int nt = 0; nt < 4; nt++) acc2[mt][nt] = make_float4(0, 0, 0, 0);
    for (int kc = 0; kc < 8; kc++) {
        __syncthreads();
        stage16(sWh, sWl, hi2, lo2, kc * 16, 128, 132, tid);
        __syncthreads();
        mma_chunk_bf<4>(tHi, tLo, 132, rowg, kc * 16, sWh, sWl, 132, cb2, acc2, lane);
    }

    // + b2, LN(128), residual (re-read g_ea), store + scatter
    {
#pragma unroll
        for (int mt = 0; mt < 2; mt++)
#pragma unroll
            for (int nt = 0; nt < 4; nt++) {
                int C = cb2 + nt * 8 + 2 * tig;
                acc2[mt][nt].x += sP[512 + C]; acc2[mt][nt].y += sP[512 + C + 1];
                acc2[mt][nt].z += sP[512 + C]; acc2[mt][nt].w += sP[512 + C + 1];
            }
        float p[2][2] = {{0, 0}, {0, 0}};
#pragma unroll
        for (int mt = 0; mt < 2; mt++)
#pragma unroll
            for (int nt = 0; nt < 4; nt++) {
                p[mt][0] += acc2[mt][nt].x + acc2[mt][nt].y;
                p[mt][1] += acc2[mt][nt].z + acc2[mt][nt].w;
            }
#pragma unroll
        for (int mt = 0; mt < 2; mt++)
#pragma unroll
            for (int h = 0; h < 2; h++) {
                p[mt][h] += __shfl_xor_sync(0xffffffffu, p[mt][h], 1);
                p[mt][h] += __shfl_xor_sync(0xffffffffu, p[mt][h], 2);
            }
        if (tig == 0)
#pragma unroll
            for (int mt = 0; mt < 2; mt++)
#pragma unroll
                for (int h = 0; h < 2; h++)
                    sRed[(rowg + mt * 16 + h * 8 + g) * 4 + wcol] = p[mt][h];
        __syncthreads();
        float m[2][2];
#pragma unroll
        for (int mt = 0; mt < 2; mt++)
#pragma unroll
            for (int h = 0; h < 2; h++) {
                float4 s = *(const float4*)&sRed[(rowg + mt * 16 + h * 8 + g) * 4];
                m[mt][h] = (s.x + s.y + s.z + s.w) * (1.0f / 128);
            }
        float q[2][2] = {{0, 0}, {0, 0}};
#pragma unroll
        for (int mt = 0; mt < 2; mt++)
#pragma unroll
            for (int nt = 0; nt < 4; nt++) {
                float dx = acc2[mt][nt].x - m[mt][0], dy = acc2[mt][nt].y - m[mt][0];
                float dz = acc2[mt][nt].z - m[mt][1], dw = acc2[mt][nt].w - m[mt][1];
                q[mt][0] += dx * dx + dy * dy;
                q[mt][1] += dz * dz + dw * dw;
            }
#pragma unroll
        for (int mt = 0; mt < 2; mt++)
#pragma unroll
            for (int h = 0; h < 2; h++) {
                q[mt][h] += __shfl_xor_sync(0xffffffffu, q[mt][h], 1);
                q[mt][h] += __shfl_xor_sync(0xffffffffu, q[mt][h], 2);
            }
        if (tig == 0)
#pragma unroll
            for (int mt = 0; mt < 2; mt++)
#pragma unroll
                for (int h = 0; h < 2; h++)
                    sRed[256 + (rowg + mt * 16 + h * 8 + g) * 4 + wcol] = q[mt][h];
        __syncthreads();
        float rn[2][2];
#pragma unroll
        for (int mt = 0; mt < 2; mt++)
#pragma unroll
            for (int h = 0; h < 2; h++) {
                float4 s = *(const float4*)&sRed[256 + (rowg + mt * 16 + h * 8 + g) * 4];
                rn[mt][h] = rsqrtf((s.x + s.y + s.z + s.w) * (1.0f / 128) + 1e-5f);
            }
#pragma unroll
        for (int mt = 0; mt < 2; mt++) {
            int r0 = rowg + mt * 16 + g;
            int r1 = r0 + 8;
#pragma unroll
            for (int nt = 0; nt < 4; nt++) {
                int C = cb2 + nt * 8 + 2 * tig;
                float gx = sP[640 + C], gy = sP[640 + C + 1];
                float bx = sP[768 + C], by = sP[768 + C + 1];
                float2 e0 = *(const float2*)&g_ea[(size_t)(base + r0) * HD + C];
                float2 e1 = *(const float2*)&g_ea[(size_t)(base + r1) * HD + C];
                float ox = e0.x + (acc2[mt][nt].x - m[mt][0]) * rn[mt][0] * gx + bx;
                float oy = e0.y + (acc2[mt][nt].y - m[mt][0]) * rn[mt][0] * gy + by;
                float oz = e1.x + (acc2[mt][nt].z - m[mt][1]) * rn[mt][1] * gx + bx;
                float ow = e1.y + (acc2[mt][nt].w - m[mt][1]) * rn[mt][1] * gy + by;
                *(float2*)&g_ea[(size_t)(base + r0) * HD + C] = make_float2(ox, oy);
                *(float2*)&g_ea[(size_t)(base + r1) * HD + C] = make_float2(oz, ow);
                float* a0 = &g_agg[(size_t)sCol[r0] * HD + C];
                float* a1 = &g_agg[(size_t)sCol[r1] * HD + C];
                asm volatile("red.global.add.v2.f32 [%0], {%1,%2};"
                             :: "l"(a0), "f"(ox), "f"(oy) : "memory");
                asm volatile("red.global.add.v2.f32 [%0], {%1,%2};"
                             :: "l"(a1), "f"(oz), "f"(ow) : "memory");
            }
        }
    }
}

// ---------------- fused node update ----------------
__global__ void __launch_bounds__(256, 2) k_node(
    int w1Off, int w2Off,
    const float* __restrict__ b1, const float* __restrict__ g1,
    const float* __restrict__ bt1, const float* __restrict__ b2,
    const float* __restrict__ g2, const float* __restrict__ bt2) {
    extern __shared__ float sm[];
    uint32_t* aHi = (uint32_t*)sm;            // 64 x 132 packed (K=256)
    uint32_t* aLo = aHi + 64 * 132;
    uint32_t* sWh = aHi + 2 * 64 * 132;       // 16 x 260
    uint32_t* sWl = sWh + 16 * 260;
    uint32_t* tHi = aHi;                      // alias after GEMM1
    uint32_t* tLo = aLo;
    __shared__ __align__(16) float sRed[512];
    __shared__ float sP[1152];
    int tid = threadIdx.x, lane = tid & 31, wid = tid >> 5;
    int g = lane >> 2, tig = lane & 3;
    int base = blockIdx.x * 64;
    const uint32_t* hi1 = g_Wb + w1Off;
    const uint32_t* lo1 = hi1 + 32768;
    const uint32_t* hi2 = g_Wb + w2Off;
    const uint32_t* lo2 = hi2 + 16384;

    for (int t = tid; t < 1152; t += 256)
        sP[t] = (t < 256) ? b1[t] : (t < 512) ? g1[t - 256] : (t < 768) ? bt1[t - 512]
              : (t < 896) ? b2[t - 768] : (t < 1024) ? g2[t - 896] : bt2[t - 1024];

    for (int t = tid; t < 64 * 32; t += 256) {   // h -> packed cols 0..63
        int i = t >> 5, q = t & 31;
        int n = base + i;
        float4 v = (n < NN) ? ((const float4*)g_h)[(size_t)n * 32 + q]
                            : make_float4(0, 0, 0, 0);
        uint32_t h0, l0, h1, l1;
        split2(v.x, v.y, h0, l0);
        split2(v.z, v.w, h1, l1);
        aHi[i * 132 + 2 * q] = h0; aHi[i * 132 + 2 * q + 1] = h1;
        aLo[i * 132 + 2 * q] = l0; aLo[i * 132 + 2 * q + 1] = l1;
    }
    for (int t = tid; t < 64 * 32; t += 256) {   // agg*inv -> packed cols 64..127
        int i = t >> 5, q = t & 31;
        int n = base + i;
        float4 v = make_float4(0, 0, 0, 0);
        if (n < NN) {
            float4* ap = (float4*)&g_agg[(size_t)n * HD + q * 4];
            v = *ap;
            float iv = g_inv[n];
            v.x *= iv; v.y *= iv; v.z *= iv; v.w *= iv;
            *ap = make_float4(0, 0, 0, 0);
        }
        uint32_t h0, l0, h1, l1;
        split2(v.x, v.y, h0, l0);
        split2(v.z, v.w, h1, l1);
        aHi[i * 132 + 64 + 2 * q] = h0; aHi[i * 132 + 64 + 2 * q + 1] = h1;
        aLo[i * 132 + 64 + 2 * q] = l0; aLo[i * 132 + 64 + 2 * q + 1] = l1;
    }
    __syncthreads();

    int rowg = (wid >> 2) * 32;
    int cb1 = (wid & 3) * 64;
    int wcol = wid & 3;

    // GEMM1 (M=64, N=256, K=256), acc init = b1
    float4 acc[2][8];
#pragma unroll
    for (int mt = 0; mt < 2; mt++)
#pragma unroll
        for (int nt = 0; nt < 8; nt++) {
            int C = cb1 + nt * 8 + 2 * tig;
            acc[mt][nt] = make_float4(sP[C], sP[C + 1], sP[C], sP[C + 1]);
        }
    for (int kc = 0; kc < 8; kc++) {
        __syncthreads();
        stage16(sWh, sWl, hi1, lo1, kc * 16, 256, 260, tid);
        __syncthreads();
        mma_chunk_bf<8>(aHi, aLo, 132, rowg, kc * 16, sWh, sWl, 260, cb1, acc, lane);
    }

    // LN(256) + GELU -> t packed (aliased on A)
    {
        float p[2][2] = {{0, 0}, {0, 0}};
#pragma unroll
        for (int mt = 0; mt < 2; mt++)
#pragma unroll
            for (int nt = 0; nt < 8; nt++) {
                p[mt][0] += acc[mt][nt].x + acc[mt][nt].y;
                p[mt][1] += acc[mt][nt].z + acc[mt][nt].w;
            }
#pragma unroll
        for (int mt = 0; mt < 2; mt++)
#pragma unroll
            for (int h = 0; h < 2; h++) {
                p[mt][h] += __shfl_xor_sync(0xffffffffu, p[mt][h], 1);
                p[mt][h] += __shfl_xor_sync(0xffffffffu, p[mt][h], 2);
            }
        if (tig == 0)
#pragma unroll
            for (int mt = 0; mt < 2; mt++)
#pragma unroll
                for (int h = 0; h < 2; h++)
                    sRed[(rowg + mt * 16 + h * 8 + g) * 4 + wcol] = p[mt][h];
        __syncthreads();
        float m[2][2];
#pragma unroll
        for (int mt = 0; mt < 2; mt++)
#pragma unroll
            for (int h = 0; h < 2; h++) {
                float4 s = *(const float4*)&sRed[(rowg + mt * 16 + h * 8 + g) * 4];
                m[mt][h] = (s.x + s.y + s.z + s.w) * (1.0f / 256);
            }
        float q[2][2] = {{0, 0}, {0, 0}};
#pragma unroll
        for (int mt = 0; mt < 2; mt++)
#pragma unroll
            for (int nt = 0; nt < 8; nt++) {
                float dx = acc[mt][nt].x - m[mt][0], dy = acc[mt][nt].y - m[mt][0];
                float dz = acc[mt][nt].z - m[mt][1], dw = acc[mt][nt].w - m[mt][1];
                q[mt][0] += dx * dx + dy * dy;
                q[mt][1] += dz * dz + dw * dw;
            }
#pragma unroll
        for (int mt = 0; mt < 2; mt++)
#pragma unroll
            for (int h = 0; h < 2; h++) {
                q[mt][h] += __shfl_xor_sync(0xffffffffu, q[mt][h], 1);
                q[mt][h] += __shfl_xor_sync(0xffffffffu, q[mt][h], 2);
            }
        if (tig == 0)
#pragma unroll
            for (int mt = 0; mt < 2; mt++)
#pragma unroll
                for (int h = 0; h < 2; h++)
                    sRed[256 + (rowg + mt * 16 + h * 8 + g) * 4 + wcol] = q[mt][h];
        __syncthreads();
        float rn[2][2];
#pragma unroll
        for (int mt = 0; mt < 2; mt++)
#pragma unroll
            for (int h = 0; h < 2; h++) {
                float4 s = *(const float4*)&sRed[256 + (rowg + mt * 16 + h * 8 + g) * 4];
                rn[mt][h] = rsqrtf((s.x + s.y + s.z + s.w) * (1.0f / 256) + 1e-5f);
            }
#pragma unroll
        for (int mt = 0; mt < 2; mt++) {
            int r0 = rowg + mt * 16 + g;
#pragma unroll
            for (int nt = 0; nt < 8; nt++) {
                int C = cb1 + nt * 8 + 2 * tig;
                int cp = C >> 1;
                float gx = sP[256 + C], gy = sP[256 + C + 1];
                float bx = sP[512 + C], by = sP[512 + C + 1];
                float tx = gelu((acc[mt][nt].x - m[mt][0]) * rn[mt][0] * gx + bx);
                float ty = gelu((acc[mt][nt].y - m[mt][0]) * rn[mt][0] * gy + by);
                float tz = gelu((acc[mt][nt].z - m[mt][1]) * rn[mt][1] * gx + bx);
                float tw = gelu((acc[mt][nt].w - m[mt][1]) * rn[mt][1] * gy + by);
                uint32_t h0, l0, h1, l1;
                split2(tx, ty, h0, l0);
                split2(tz, tw, h1, l1);
                tHi[r0 * 132 + cp] = h0; tLo[r0 * 132 + cp] = l0;
                tHi[(r0 + 8) * 132 + cp] = h1; tLo[(r0 + 8) * 132 + cp] = l1;
            }
        }
    }

    // GEMM2 (M=64, N=128, K=256)
    int cb2 = (wid & 3) * 32;
    float4 acc2[2][4];
#pragma unroll
    for (int mt = 0; mt < 2; mt++)
#pragma unroll
        for (int nt = 0; nt < 4; nt++) acc2[mt][nt] = make_float4(0, 0, 0, 0);
    for (int kc = 0; kc < 8; kc++) {
        __syncthreads();
        stage16(sWh, sWl, hi2, lo2, kc * 16, 128, 132, tid);
        __syncthreads();
        mma_chunk_bf<4>(tHi, tLo, 132, rowg, kc * 16, sWh, sWl, 132, cb2, acc2, lane);
    }

    // + b2, LN(128), residual from g_h, store h
    {
#pragma unroll
        for (int mt = 0; mt < 2; mt++)
#pragma unroll
            for (int nt = 0; nt < 4; nt++) {
                int C = cb2 + nt * 8 + 2 * tig;
                acc2[mt][nt].x += sP[768 + C]; acc2[mt][nt].y += sP[768 + C + 1];
                acc2[mt][nt].z += sP[768 + C]; acc2[mt][nt].w += sP[768 + C + 1];
            }
        float p[2][2] = {{0, 0}, {0, 0}};
#pragma unroll
        for (int mt = 0; mt < 2; mt++)
#pragma unroll
            for (int nt = 0; nt < 4; nt++) {
                p[mt][0] += acc2[mt][nt].x + acc2[mt][nt].y;
                p[mt][1] += acc2[mt][nt].z + acc2[mt][nt].w;
            }
#pragma unroll
        for (int mt = 0; mt < 2; mt++)
#pragma unroll
            for (int h = 0; h < 2; h++) {
                p[mt][h] += __shfl_xor_sync(0xffffffffu, p[mt][h], 1);
                p[mt][h] += __shfl_xor_sync(0xffffffffu, p[mt][h], 2);
            }
        if (tig == 0)
#pragma unroll
            for (int mt = 0; mt < 2; mt++)
#pragma unroll
                for (int h = 0; h < 2; h++)
                    sRed[(rowg + mt * 16 + h * 8 + g) * 4 + wcol] = p[mt][h];
        __syncthreads();
        float m[2][2];
#pragma unroll
        for (int mt = 0; mt < 2; mt++)
#pragma unroll
            for (int h = 0; h < 2; h++) {
                float4 s = *(const float4*)&sRed[(rowg + mt * 16 + h * 8 + g) * 4];
                m[mt][h] = (s.x + s.y + s.z + s.w) * (1.0f / 128);
            }
        float q[2][2] = {{0, 0}, {0, 0}};
#pragma unroll
        for (int mt = 0; mt < 2; mt++)
#pragma unroll
            for (int nt = 0; nt < 4; nt++) {
                float dx = acc2[mt][nt].x - m[mt][0], dy = acc2[mt][nt].y - m[mt][0];
                float dz = acc2[mt][nt].z - m[mt][1], dw = acc2[mt][nt].w - m[mt][1];
                q[mt][0] += dx * dx + dy * dy;
                q[mt][1] += dz * dz + dw * dw;
            }
#pragma unroll
        for (int mt = 0; mt < 2; mt++)
#pragma unroll
            for (int h = 0; h < 2; h++) {
                q[mt][h] += __shfl_xor_sync(0xffffffffu, q[mt][h], 1);
                q[mt][h] += __shfl_xor_sync(0xffffffffu, q[mt][h], 2);
            }
        if (tig == 0)
#pragma unroll
            for (int mt = 0; mt < 2; mt++)
#pragma unroll
                for (int h = 0; h < 2; h++)
                    sRed[256 + (rowg + mt * 16 + h * 8 + g) * 4 + wcol] = q[mt][h];
        __syncthreads();
        float rn[2][2];
#pragma unroll
        for (int mt = 0; mt < 2; mt++)
#pragma unroll
            for (int h = 0; h < 2; h++) {
                float4 s = *(const float4*)&sRed[256 + (rowg + mt * 16 + h * 8 + g) * 4];
                rn[mt][h] = rsqrtf((s.x + s.y + s.z + s.w) * (1.0f / 128) + 1e-5f);
            }
#pragma unroll
        for (int mt = 0; mt < 2; mt++) {
            int r0 = rowg + mt * 16 + g;
            int r1 = r0 + 8;
            int n0 = base + r0, n1 = base + r1;
#pragma unroll
            for (int nt = 0; nt < 4; nt++) {
                int C = cb2 + nt * 8 + 2 * tig;
                float gx = sP[896 + C], gy = sP[896 + C + 1];
                float bx = sP[1024 + C], by = sP[1024 + C + 1];
                if (n0 < NN) {
                    float2 hr = *(const float2*)&g_h[(size_t)n0 * HD + C];
                    float ox = hr.x + (acc2[mt][nt].x - m[mt][0]) * rn[mt][0] * gx + bx;
                    float oy = hr.y + (acc2[mt][nt].y - m[mt][0]) * rn[mt][0] * gy + by;
                    *(float2*)&g_h[(size_t)n0 * HD + C] = make_float2(ox, oy);
                }
                if (n1 < NN) {
                    float2 hr = *(const float2*)&g_h[(size_t)n1 * HD + C];
                    float oz = hr.x + (acc2[mt][nt].z - m[mt][1]) * rn[mt][1] * gx + bx;
                    float ow = hr.y + (acc2[mt][nt].w - m[mt][1]) * rn[mt][1] * gy + by;
                    *(float2*)&g_h[(size_t)n1 * HD + C] = make_float2(oz, ow);
                }
            }
        }
    }
}

// ---------------- decoder ----------------
__global__ void k_dec(const float* __restrict__ W1, const float* __restrict__ b1,
                      const float* __restrict__ W2, const float* __restrict__ b2,
                      float* __restrict__ out) {
    int n = blockIdx.x, j = threadIdx.x;
    __shared__ float sh[128];
    __shared__ float st[128];
    sh[j] = g_h[(size_t)n * HD + j];
    __syncthreads();
    float a = b1[j];
#pragma unroll 8
    for (int k = 0; k < 128; k++) a = fmaf(sh[k], W1[k * HD + j], a);
    st[j] = gelu(a);
    __syncthreads();
    int w = j >> 5, lane = j & 31;
    float s = 0;
#pragma unroll
    for (int k = lane; k < 128; k += 32) s = fmaf(st[k], W2[k * 4 + w], s);
    s = warpsum(s);
    if (lane == 0) out[(size_t)n * 4 + w] = s + b2[w];
}

// ---------------- launch ----------------
extern "C" void kernel_launch(void* const* d_in, const int* in_sizes, int n_in,
                              void* d_out, int out_size) {
    (void)in_sizes; (void)n_in; (void)out_size;
    const float* x       = (const float*)d_in[0];
    const void*  ei      = d_in[1];
    const float* eattr   = (const float*)d_in[2];
    const float* enc_W   = (const float*)d_in[3];
    const float* enc_b   = (const float*)d_in[4];
    const float* enc_g   = (const float*)d_in[5];
    const float* enc_bt  = (const float*)d_in[6];
    const float* ee_W    = (const float*)d_in[7];
    const float* ee_b    = (const float*)d_in[8];
    const float* eW1     = (const float*)d_in[9];
    const float* eb1     = (const float*)d_in[10];
    const float* eg1     = (const float*)d_in[11];
    const float* ebt1    = (const float*)d_in[12];
    const float* eW2     = (const float*)d_in[13];
    const float* eb2     = (const float*)d_in[14];
    const float* eg2     = (const float*)d_in[15];
    const float* ebt2    = (const float*)d_in[16];
    const float* nW1     = (const float*)d_in[17];
    const float* nb1     = (const float*)d_in[18];
    const float* ng1     = (const float*)d_in[19];
    const float* nbt1    = (const float*)d_in[20];
    const float* nW2     = (const float*)d_in[21];
    const float* nb2     = (const float*)d_in[22];
    const float* ng2     = (const float*)d_in[23];
    const float* nbt2    = (const float*)d_in[24];
    const float* dec_W1  = (const float*)d_in[25];
    const float* dec_b1  = (const float*)d_in[26];
    const float* dec_W2  = (const float*)d_in[27];
    const float* dec_b2  = (const float*)d_in[28];

    cudaFuncSetAttribute(k_edge, cudaFuncAttributeMaxDynamicSharedMemorySize, EDGE_SMEM);
    cudaFuncSetAttribute(k_node, cudaFuncAttributeMaxDynamicSharedMemorySize, NODE_SMEM);
    cudaFuncSetAttribute(k_P,    cudaFuncAttributeMaxDynamicSharedMemorySize, P_SMEM);

    // pre-split weights into packed bf16 hi/lo planes (once per launch)
    {
        uint32_t* wb = nullptr;
        cudaGetSymbolAddress((void**)&wb, g_Wb);
        k_prep<<<dim3(192, 10), 256>>>(eW1, wb + EW1_OFF, 192, 256, 98304, 98304);
        k_prep<<<dim3(64, 10), 256>>>(eW2, wb + EW2_OFF, 128, 128, 32768, 32768);
        k_prep<<<dim3(128, 10), 256>>>(nW1, wb + NW1_OFF, 128, 256, 65536, 65536);
        k_prep<<<dim3(64, 10), 256>>>(nW2, wb + NW2_OFF, 128, 128, 32768, 32768);
    }

    k_detect<<<1, 32>>>(ei);
    k_convert<<<(NE + 255) / 256, 256>>>(ei);
    k_inv<<<(NN + 255) / 256, 256>>>();
    k_enc<<<NN, 128>>>(x, enc_W, enc_b, enc_g, enc_bt);
    k_ee<<<NE, 128>>>(eattr, ee_W, ee_b);

    const int nodeBlocks = (NN + 63) / 64;  // 782
    for (int l = 0; l < 10; l++) {
        k_P<<<dim3(nodeBlocks, 2), 256, P_SMEM>>>(EW1_OFF + l * 98304, eb1 + l * 256);
        k_edge<<<NE / 64, 256, EDGE_SMEM>>>(
            EW1_OFF + l * 98304, EW2_OFF + l * 32768,
            eg1 + l * 256, ebt1 + l * 256,
            eb2 + l * 128, eg2 + l * 128, ebt2 + l * 128);
        k_node<<<nodeBlocks, 256, NODE_SMEM>>>(
            NW1_OFF + l * 65536, NW2_OFF + l * 32768,
            nb1 + l * 256, ng1 + l * 256, nbt1 + l * 256,
            nb2 + l * 128, ng2 + l * 128, nbt2 + l * 128);
    }
    k_dec<<<NN, 128>>>(dec_W1, dec_b1, dec_W2, dec_b2, (float*)d_out);
}